// round 1
// baseline (speedup 1.0000x reference)
#include <cuda_runtime.h>
#include <math.h>

#define BATCH 4
#define SEQ   2048
#define NH    16
#define HD    128
#define DM    2048
#define MROWS (BATCH*SEQ)

// scratch (device globals: allowed; no cudaMalloc anywhere)
__device__ float g_q[(size_t)MROWS*DM];     // q projection, (B,S,H,hd)
__device__ float g_k[(size_t)MROWS*HD];     // k projection (roped in place)
__device__ float g_attn[(size_t)MROWS*DM];  // attention output, (B,S,H,hd)

// ---------------------------------------------------------------------------
// SGEMM  C[M,N] = A[M,K] @ B[K,N] + bias[N]
// BM=BN=128, BK=8, 256 threads, 8x8 micro-tile (rows 8ty.., cols {4tx..,4tx+64..})
// ---------------------------------------------------------------------------
__global__ void __launch_bounds__(256) sgemm_bias(
    const float* __restrict__ A, const float* __restrict__ B,
    const float* __restrict__ bias, float* __restrict__ C,
    int M, int N, int K)
{
    __shared__ float As[8][132];
    __shared__ float Bs[8][132];

    const int tid = threadIdx.x;
    const int tx = tid & 15, ty = tid >> 4;
    const int bm = blockIdx.y, bn = blockIdx.x;

    const int ar = tid >> 1,  ac = (tid & 1) * 4;   // A tile: row, k-col
    const int br = tid >> 5,  bc = (tid & 31) * 4;  // B tile: k-row, n-col

    const float* Ap = A + (size_t)(bm*128 + ar) * K + ac;
    const float* Bp = B + (size_t)br * N + bn*128 + bc;

    float acc[8][8];
    #pragma unroll
    for (int r = 0; r < 8; r++)
        #pragma unroll
        for (int c = 0; c < 8; c++) acc[r][c] = 0.f;

    for (int kt = 0; kt < K; kt += 8) {
        float4 a4 = *(const float4*)(Ap + kt);
        float4 b4 = *(const float4*)(Bp + (size_t)kt * N);
        __syncthreads();
        As[ac+0][ar] = a4.x; As[ac+1][ar] = a4.y;
        As[ac+2][ar] = a4.z; As[ac+3][ar] = a4.w;
        *(float4*)&Bs[br][bc] = b4;
        __syncthreads();
        #pragma unroll
        for (int kk = 0; kk < 8; kk++) {
            float4 a0 = *(const float4*)&As[kk][ty*8];
            float4 a1 = *(const float4*)&As[kk][ty*8+4];
            float4 b0 = *(const float4*)&Bs[kk][tx*4];
            float4 b1 = *(const float4*)&Bs[kk][tx*4+64];
            float av[8] = {a0.x,a0.y,a0.z,a0.w,a1.x,a1.y,a1.z,a1.w};
            float bw[8] = {b0.x,b0.y,b0.z,b0.w,b1.x,b1.y,b1.z,b1.w};
            #pragma unroll
            for (int r = 0; r < 8; r++)
                #pragma unroll
                for (int c = 0; c < 8; c++)
                    acc[r][c] += av[r] * bw[c];
        }
    }

    float4 bv0 = *(const float4*)(bias + bn*128 + tx*4);
    float4 bv1 = *(const float4*)(bias + bn*128 + tx*4 + 64);
    #pragma unroll
    for (int r = 0; r < 8; r++) {
        size_t row = (size_t)(bm*128 + ty*8 + r);
        float* cp = C + row * N + bn*128;
        float4 o0 = make_float4(acc[r][0]+bv0.x, acc[r][1]+bv0.y,
                                acc[r][2]+bv0.z, acc[r][3]+bv0.w);
        float4 o1 = make_float4(acc[r][4]+bv1.x, acc[r][5]+bv1.y,
                                acc[r][6]+bv1.z, acc[r][7]+bv1.w);
        *(float4*)(cp + tx*4)      = o0;
        *(float4*)(cp + tx*4 + 64) = o1;
    }
}

// ---------------------------------------------------------------------------
// RoPE
// ---------------------------------------------------------------------------
__global__ void rope_q_kernel(float* __restrict__ q)
{
    int idx = blockIdx.x * blockDim.x + threadIdx.x;   // over B*S*H*64
    int i = idx & 63;
    int s = (idx >> 10) & 2047;
    float inv = 1.0f / powf(10000.0f, (float)(2*i) * (1.0f/128.0f));
    float ang = (float)s * inv;
    float sn, cs;
    sincosf(ang, &sn, &cs);
    float2 v = *(float2*)(q + 2*(size_t)idx);
    float x1 = v.x, x2 = v.y;
    v.x = x1*cs - x2*sn;
    v.y = x1*sn + x2*cs;
    *(float2*)(q + 2*(size_t)idx) = v;
}

__global__ void rope_k_kernel(float* __restrict__ k, float* __restrict__ kh)
{
    int idx = blockIdx.x * blockDim.x + threadIdx.x;   // over B*S*64
    int i = idx & 63;
    int s = (idx >> 6) & 2047;
    float inv = 1.0f / powf(10000.0f, (float)(2*i) * (1.0f/128.0f));
    float ang = (float)s * inv;
    float sn, cs;
    sincosf(ang, &sn, &cs);
    float2 v = *(float2*)(k + 2*(size_t)idx);
    float x1 = v.x, x2 = v.y;
    v.x = x1*cs - x2*sn;
    v.y = x1*sn + x2*cs;
    *(float2*)(k + 2*(size_t)idx)  = v;
    *(float2*)(kh + 2*(size_t)idx) = v;
}

// ---------------------------------------------------------------------------
// Causal MQA flash attention (fp32).
// Block: 512 thr (tx=tid&15 -> kv cols / out dims, ty=tid>>4 -> q rows)
// BM=128 q rows, BN=64 kv per tile. Thread owns rows {ty+32rr}, cols {tx+16jj}.
// ---------------------------------------------------------------------------
#define ATT_SCALE 0.08838834764831845f

__global__ void __launch_bounds__(512) flash_attn(
    const float* __restrict__ Q, const float* __restrict__ K,
    const float* __restrict__ V, float* __restrict__ O)
{
    extern __shared__ float smbuf[];
    float* Qs = smbuf;              // 128*128
    float* Ks = Qs + 128*128;       // 64*132 (padded)
    float* Vs = Ks + 64*132;        // 64*128
    float* Ps = Vs + 64*128;        // 128*66 (padded)

    const int tid = threadIdx.x;
    const int tx = tid & 15, ty = tid >> 4;
    const int b = blockIdx.z, h = blockIdx.y;
    const int row0 = blockIdx.x * 128;

    // load Q tile (128 rows x 128)
    #pragma unroll
    for (int it = 0; it < 8; it++) {
        int i = tid + it*512;
        int r = i >> 5, c = (i & 31) << 2;
        *(float4*)&Qs[r*128 + c] =
            *(const float4*)&Q[(((size_t)b*SEQ + row0 + r)*NH + h)*HD + c];
    }

    float m[4], l[4], o[4][8];
    #pragma unroll
    for (int rr = 0; rr < 4; rr++) {
        m[rr] = -INFINITY; l[rr] = 0.f;
        #pragma unroll
        for (int d = 0; d < 8; d++) o[rr][d] = 0.f;
    }

    const int n_tiles = 2*blockIdx.x + 2;
    for (int t = 0; t < n_tiles; t++) {
        const int kb = t * 64;
        __syncthreads();   // prev-tile consumers done (also covers Q-load on t=0)
        #pragma unroll
        for (int it = 0; it < 4; it++) {
            int i = tid + it*512;
            int r = i >> 5, c = (i & 31) << 2;
            size_t g = ((size_t)b*SEQ + kb + r)*HD + c;
            *(float4*)&Ks[r*132 + c] = *(const float4*)&K[g];
            *(float4*)&Vs[r*128 + c] = *(const float4*)&V[g];
        }
        __syncthreads();

        // S = Q K^T (4x4 strided micro-tile)
        float s[4][4];
        #pragma unroll
        for (int rr = 0; rr < 4; rr++)
            #pragma unroll
            for (int jj = 0; jj < 4; jj++) s[rr][jj] = 0.f;

        #pragma unroll
        for (int dc = 0; dc < 32; dc++) {
            float4 a[4], kv[4];
            #pragma unroll
            for (int rr = 0; rr < 4; rr++)
                a[rr] = *(const float4*)&Qs[(ty + 32*rr)*128 + dc*4];
            #pragma unroll
            for (int jj = 0; jj < 4; jj++)
                kv[jj] = *(const float4*)&Ks[(tx + 16*jj)*132 + dc*4];
            #pragma unroll
            for (int rr = 0; rr < 4; rr++)
                #pragma unroll
                for (int jj = 0; jj < 4; jj++)
                    s[rr][jj] += a[rr].x*kv[jj].x + a[rr].y*kv[jj].y
                               + a[rr].z*kv[jj].z + a[rr].w*kv[jj].w;
        }

        // causal mask + online softmax (per owned row; reduce across 16-lane group)
        #pragma unroll
        for (int rr = 0; rr < 4; rr++) {
            const int r = row0 + ty + 32*rr;
            float tmax = -INFINITY;
            #pragma unroll
            for (int jj = 0; jj < 4; jj++) {
                int j = kb + tx + 16*jj;
                float sv = (j <= r) ? s[rr][jj]*ATT_SCALE : -INFINITY;
                s[rr][jj] = sv;
                tmax = fmaxf(tmax, sv);
            }
            #pragma unroll
            for (int off = 8; off; off >>= 1)
                tmax = fmaxf(tmax, __shfl_xor_sync(0xffffffffu, tmax, off, 16));
            float mn = fmaxf(m[rr], tmax);
            float rsum = 0.f;
            #pragma unroll
            for (int jj = 0; jj < 4; jj++) {
                float p = __expf(s[rr][jj] - mn);
                s[rr][jj] = p;
                rsum += p;
            }
            #pragma unroll
            for (int off = 8; off; off >>= 1)
                rsum += __shfl_xor_sync(0xffffffffu, rsum, off, 16);
            float alpha = __expf(m[rr] - mn);
            m[rr] = mn;
            l[rr] = l[rr]*alpha + rsum;
            #pragma unroll
            for (int d = 0; d < 8; d++) o[rr][d] *= alpha;
            #pragma unroll
            for (int jj = 0; jj < 4; jj++)
                Ps[(ty + 32*rr)*66 + tx + 16*jj] = s[rr][jj];
        }
        __syncthreads();

        // O += P @ V
        #pragma unroll 4
        for (int j = 0; j < 64; j++) {
            float4 v0 = *(const float4*)&Vs[j*128 + tx*4];
            float4 v1 = *(const float4*)&Vs[j*128 + tx*4 + 64];
            #pragma unroll
            for (int rr = 0; rr < 4; rr++) {
                float p = Ps[(ty + 32*rr)*66 + j];
                o[rr][0] += p*v0.x; o[rr][1] += p*v0.y;
                o[rr][2] += p*v0.z; o[rr][3] += p*v0.w;
                o[rr][4] += p*v1.x; o[rr][5] += p*v1.y;
                o[rr][6] += p*v1.z; o[rr][7] += p*v1.w;
            }
        }
    }

    #pragma unroll
    for (int rr = 0; rr < 4; rr++) {
        float inv = 1.0f / l[rr];
        size_t base = (((size_t)b*SEQ + row0 + ty + 32*rr)*NH + h)*HD;
        float4 w0 = make_float4(o[rr][0]*inv, o[rr][1]*inv, o[rr][2]*inv, o[rr][3]*inv);
        float4 w1 = make_float4(o[rr][4]*inv, o[rr][5]*inv, o[rr][6]*inv, o[rr][7]*inv);
        *(float4*)&O[base + tx*4]      = w0;
        *(float4*)&O[base + tx*4 + 64] = w1;
    }
}

// ---------------------------------------------------------------------------
extern "C" void kernel_launch(void* const* d_in, const int* in_sizes, int n_in,
                              void* d_out, int out_size)
{
    const float* x  = (const float*)d_in[0];
    const float* wq = (const float*)d_in[1];
    const float* bq = (const float*)d_in[2];
    const float* wk = (const float*)d_in[3];
    const float* bk = (const float*)d_in[4];
    const float* wv = (const float*)d_in[5];
    const float* bv = (const float*)d_in[6];
    const float* wo = (const float*)d_in[7];
    const float* bo = (const float*)d_in[8];

    float* out = (float*)d_out;                      // (B,S,D)
    float* kh  = out + (size_t)MROWS*DM;             // (B,1,S,HD)
    float* vh  = kh  + (size_t)MROWS*HD;             // (B,1,S,HD)

    float *qp, *kp, *ap;
    cudaGetSymbolAddress((void**)&qp, g_q);
    cudaGetSymbolAddress((void**)&kp, g_k);
    cudaGetSymbolAddress((void**)&ap, g_attn);

    const int FLASH_SMEM = (128*128 + 64*132 + 64*128 + 128*66) * 4; // 165,888 B
    cudaFuncSetAttribute(flash_attn, cudaFuncAttributeMaxDynamicSharedMemorySize,
                         FLASH_SMEM);

    // projections
    sgemm_bias<<<dim3(16, 64), 256>>>(x, wq, bq, qp, MROWS, DM, DM);
    sgemm_bias<<<dim3(1,  64), 256>>>(x, wk, bk, kp, MROWS, HD, DM);
    sgemm_bias<<<dim3(1,  64), 256>>>(x, wv, bv, vh, MROWS, HD, DM);  // vh output directly

    // rope
    rope_q_kernel<<<(MROWS*NH*64)/256, 256>>>(qp);
    rope_k_kernel<<<(MROWS*64)/256, 256>>>(kp, kh);

    // attention
    flash_attn<<<dim3(16, 16, 4), 512, FLASH_SMEM>>>(qp, kp, vh, ap);

    // output projection
    sgemm_bias<<<dim3(16, 64), 256>>>(ap, wo, bo, out, MROWS, DM, DM);
}

// round 3
// speedup vs baseline: 1.5993x; 1.5993x over previous
#include <cuda_runtime.h>
#include <cuda_bf16.h>
#include <math.h>

#define BATCH 4
#define SEQ   2048
#define NH    16
#define HD    128
#define DM    2048
#define MROWS (BATCH*SEQ)
#define KDIM  2048
#define NCHUNK (KDIM/64)

// ---------------------------------------------------------------------------
// scratch (device globals; no cudaMalloc anywhere)
// ---------------------------------------------------------------------------
__device__ float g_q[(size_t)MROWS*DM];     // q projection (roped in place)
__device__ float g_k[(size_t)MROWS*HD];     // k projection (roped in place)
__device__ float g_attn[(size_t)MROWS*DM];  // attention output
__device__ __nv_bfloat16 g_ahi[(size_t)MROWS*DM];   // split activations
__device__ __nv_bfloat16 g_alo[(size_t)MROWS*DM];
__device__ __nv_bfloat16 g_wqT_hi[(size_t)DM*DM], g_wqT_lo[(size_t)DM*DM];
__device__ __nv_bfloat16 g_woT_hi[(size_t)DM*DM], g_woT_lo[(size_t)DM*DM];
__device__ __nv_bfloat16 g_wkT_hi[(size_t)HD*DM], g_wkT_lo[(size_t)HD*DM];
__device__ __nv_bfloat16 g_wvT_hi[(size_t)HD*DM], g_wvT_lo[(size_t)HD*DM];

// ---------------------------------------------------------------------------
// common helpers
// ---------------------------------------------------------------------------
__device__ __forceinline__ unsigned s2u(const void* p) {
    unsigned a;
    asm("{ .reg .u64 t; cvta.to.shared.u64 t, %1; cvt.u32.u64 %0, t; }"
        : "=r"(a) : "l"(p));
    return a;
}

#if defined(__CUDA_ARCH_FEAT_SM103_ALL)
// --------------------------- tcgen05 helpers --------------------------------
__device__ __forceinline__ unsigned elect1() {
    unsigned p;
    asm volatile("{ .reg .pred p; elect.sync _|p, 0xFFFFFFFF; selp.b32 %0,1,0,p; }"
                 : "=r"(p));
    return p;
}
__device__ __forceinline__ void mbar_init(unsigned a, unsigned cnt) {
    asm volatile("mbarrier.init.shared.b64 [%0], %1;" :: "r"(a), "r"(cnt) : "memory");
}
__device__ __forceinline__ void mbar_inval(unsigned a) {
    asm volatile("mbarrier.inval.shared.b64 [%0];" :: "r"(a) : "memory");
}
__device__ __forceinline__ void mbar_wait(unsigned a, unsigned ph) {
    asm volatile(
        "{\n\t.reg .pred P;\n\t"
        "WL%=:\n\t"
        "mbarrier.try_wait.parity.acquire.cta.shared::cta.b64 P, [%0], %1, 0x989680;\n\t"
        "@P bra WD%=;\n\t"
        "bra WL%=;\n\t"
        "WD%=:\n\t}"
        :: "r"(a), "r"(ph) : "memory");
}
__device__ __forceinline__ void tc_alloc(unsigned smem_dst, unsigned ncols) {
    asm volatile("tcgen05.alloc.cta_group::1.sync.aligned.shared::cta.b32 [%0], %1;"
                 :: "r"(smem_dst), "r"(ncols) : "memory");
}
__device__ __forceinline__ void tc_dealloc(unsigned tmem, unsigned ncols) {
    asm volatile("tcgen05.dealloc.cta_group::1.sync.aligned.b32 %0, %1;"
                 :: "r"(tmem), "r"(ncols));
}
__device__ __forceinline__ void tc_commit(unsigned mbar) {
    asm volatile("tcgen05.commit.cta_group::1.mbarrier::arrive::one.shared::cluster.b64 [%0];"
                 :: "r"(mbar) : "memory");
}
__device__ __forceinline__ void tc_fence_after() {
    asm volatile("tcgen05.fence::after_thread_sync;" ::: "memory");
}
__device__ __forceinline__ void tc_fence_before() {
    asm volatile("tcgen05.fence::before_thread_sync;" ::: "memory");
}
__device__ __forceinline__ void tc_wait_ld() {
    asm volatile("tcgen05.wait::ld.sync.aligned;" ::: "memory");
}
__device__ __forceinline__ void fence_proxy_async_cta() {
    asm volatile("fence.proxy.async.shared::cta;" ::: "memory");
}
__device__ __forceinline__ void mma_f16_ss(unsigned d, unsigned long long a_desc,
                                           unsigned long long b_desc, unsigned idesc,
                                           unsigned en) {
    asm volatile(
        "{\n\t.reg .pred p;\n\t"
        "setp.ne.u32 p, %5, 0;\n\t"
        "tcgen05.mma.cta_group::1.kind::f16 [%0], %1, %2, %3, {%4,%4,%4,%4}, p;\n\t"
        "}"
        :: "r"(d), "l"(a_desc), "l"(b_desc), "r"(idesc), "r"(0u), "r"(en)
        : "memory");
}
#define TC_LD_32X32B_X32(r, tmem_addr) \
    asm volatile( \
        "tcgen05.ld.sync.aligned.32x32b.x32.b32 " \
        "{%0, %1, %2, %3, %4, %5, %6, %7, " \
        " %8, %9, %10, %11, %12, %13, %14, %15, " \
        " %16, %17, %18, %19, %20, %21, %22, %23, " \
        " %24, %25, %26, %27, %28, %29, %30, %31}, [%32];" \
        : "=r"((r)[0]),  "=r"((r)[1]),  "=r"((r)[2]),  "=r"((r)[3]), \
          "=r"((r)[4]),  "=r"((r)[5]),  "=r"((r)[6]),  "=r"((r)[7]), \
          "=r"((r)[8]),  "=r"((r)[9]),  "=r"((r)[10]), "=r"((r)[11]), \
          "=r"((r)[12]), "=r"((r)[13]), "=r"((r)[14]), "=r"((r)[15]), \
          "=r"((r)[16]), "=r"((r)[17]), "=r"((r)[18]), "=r"((r)[19]), \
          "=r"((r)[20]), "=r"((r)[21]), "=r"((r)[22]), "=r"((r)[23]), \
          "=r"((r)[24]), "=r"((r)[25]), "=r"((r)[26]), "=r"((r)[27]), \
          "=r"((r)[28]), "=r"((r)[29]), "=r"((r)[30]), "=r"((r)[31]) \
        : "r"(tmem_addr))
__device__ __forceinline__ unsigned long long make_desc(unsigned addr) {
    const unsigned long long BASE =
        (2ULL << 61) | (1ULL << 46) | (64ULL << 32) | (1ULL << 16);
    return BASE | (unsigned long long)((addr >> 4) & 0x3FFF);
}
#define GEMM_IDESC 0x8200490u
#else
// --------------------------- mma.sync helpers -------------------------------
__device__ __forceinline__ void ldmx4(unsigned r[4], unsigned addr) {
    asm volatile("ldmatrix.sync.aligned.m8n8.x4.shared.b16 {%0,%1,%2,%3}, [%4];"
                 : "=r"(r[0]), "=r"(r[1]), "=r"(r[2]), "=r"(r[3]) : "r"(addr));
}
__device__ __forceinline__ void ldmx2(unsigned r[2], unsigned addr) {
    asm volatile("ldmatrix.sync.aligned.m8n8.x2.shared.b16 {%0,%1}, [%2];"
                 : "=r"(r[0]), "=r"(r[1]) : "r"(addr));
}
__device__ __forceinline__ void mma_bf16(float c[4], const unsigned a[4],
                                         const unsigned b[2]) {
    asm volatile(
        "mma.sync.aligned.m16n8k16.row.col.f32.bf16.bf16.f32 "
        "{%0,%1,%2,%3}, {%4,%5,%6,%7}, {%8,%9}, {%0,%1,%2,%3};"
        : "+f"(c[0]), "+f"(c[1]), "+f"(c[2]), "+f"(c[3])
        : "r"(a[0]), "r"(a[1]), "r"(a[2]), "r"(a[3]), "r"(b[0]), "r"(b[1]));
}
#endif

// ---------------------------------------------------------------------------
// tensor-core bf16x3 GEMM:  C[M,Ntot] = (Ahi+Alo)[M,K] @ (Bhi+Blo)[Ntot,K]^T + bias
// BM=BN=128, BK=64 (SW128 smem), 256 threads.
// tcgen05 path when compiled for sm_103a; mma.sync HMMA fallback otherwise.
// ---------------------------------------------------------------------------
__global__ void __launch_bounds__(256) gemm_tc(
    const __nv_bfloat16* __restrict__ Ahi, const __nv_bfloat16* __restrict__ Alo,
    const __nv_bfloat16* __restrict__ Bhi, const __nv_bfloat16* __restrict__ Blo,
    const float* __restrict__ bias, float* __restrict__ C, int Ntot)
{
    extern __shared__ __align__(1024) char smem[];
    const unsigned sb = s2u(smem);
    const int tid = threadIdx.x;
    const int m0 = blockIdx.y * 128;
    const int n0 = blockIdx.x * 128;

#if defined(__CUDA_ARCH_FEAT_SM103_ALL)
    // ---------------- tcgen05 path: double-buffered, TMEM accumulator -------
    if (tid == 0) { mbar_init(sb + 16, 1); mbar_init(sb + 24, 1); }
    if (tid < 32) tc_alloc(sb, 128);
    __syncthreads();
    unsigned tmem;
    asm volatile("ld.shared.b32 %0, [%1];" : "=r"(tmem) : "r"(sb));

    for (int c = 0; c < NCHUNK; c++) {
        const int buf = c & 1;
        const unsigned tb = 1024u + buf * 65536u;
        if (c >= 2) mbar_wait(sb + 16 + buf * 8, ((c >> 1) - 1) & 1);

        const int k0 = c * 64;
        char* smA_hi = smem + tb;
        char* smA_lo = smem + tb + 16384;
        char* smB_hi = smem + tb + 32768;
        char* smB_lo = smem + tb + 49152;
        #pragma unroll
        for (int t = 0; t < 4; t++) {
            int i = tid + t * 256;
            int rr = i >> 3, q = i & 7;
            size_t ga = (size_t)(m0 + rr) * KDIM + k0 + q * 8;
            size_t gb = (size_t)(n0 + rr) * KDIM + k0 + q * 8;
            int so = rr * 128 + q * 16;
            int sw = so ^ ((so >> 3) & 0x70);
            *(uint4*)(smA_hi + sw) = *(const uint4*)(Ahi + ga);
            *(uint4*)(smA_lo + sw) = *(const uint4*)(Alo + ga);
            *(uint4*)(smB_hi + sw) = *(const uint4*)(Bhi + gb);
            *(uint4*)(smB_lo + sw) = *(const uint4*)(Blo + gb);
        }
        fence_proxy_async_cta();
        __syncthreads();

        if (tid < 32 && elect1()) {
            unsigned long long dAh = make_desc(sb + tb);
            unsigned long long dAl = make_desc(sb + tb + 16384);
            unsigned long long dBh = make_desc(sb + tb + 32768);
            unsigned long long dBl = make_desc(sb + tb + 49152);
            #pragma unroll
            for (int k = 0; k < 4; k++) {
                unsigned en0 = (c == 0 && k == 0) ? 0u : 1u;
                mma_f16_ss(tmem, dAh + k * 2, dBh + k * 2, GEMM_IDESC, en0);
                mma_f16_ss(tmem, dAh + k * 2, dBl + k * 2, GEMM_IDESC, 1u);
                mma_f16_ss(tmem, dAl + k * 2, dBh + k * 2, GEMM_IDESC, 1u);
            }
            tc_commit(sb + 16 + buf * 8);
        }
    }

    mbar_wait(sb + 16, ((NCHUNK - 2) >> 1) & 1);
    mbar_wait(sb + 24, ((NCHUNK - 1) >> 1) & 1);
    tc_fence_after();

    if (tid < 128) {
        const int w = tid >> 5, l = tid & 31;
        const size_t row = (size_t)m0 + w * 32 + l;
        #pragma unroll
        for (int c0 = 0; c0 < 128; c0 += 32) {
            unsigned dr[32];
            TC_LD_32X32B_X32(dr, tmem + c0);
            tc_wait_ld();
            float* cp = C + row * Ntot + n0 + c0;
            #pragma unroll
            for (int c = 0; c < 32; c += 4) {
                float4 o;
                o.x = __uint_as_float(dr[c+0]) + bias[n0 + c0 + c + 0];
                o.y = __uint_as_float(dr[c+1]) + bias[n0 + c0 + c + 1];
                o.z = __uint_as_float(dr[c+2]) + bias[n0 + c0 + c + 2];
                o.w = __uint_as_float(dr[c+3]) + bias[n0 + c0 + c + 3];
                *(float4*)(cp + c) = o;
            }
        }
        tc_fence_before();
    }
    __syncthreads();
    if (tid == 0) { mbar_inval(sb + 16); mbar_inval(sb + 24); }
    __syncthreads();
    if (tid < 32) tc_dealloc(tmem, 128);

#else
    // ---------------- mma.sync fallback: register accumulators --------------
    const int lane = tid & 31, w = tid >> 5;
    const int wm = w & 3, wn = w >> 2;        // warp tile: 32 (M) x 64 (N)

    float acc[2][8][4];
    #pragma unroll
    for (int mt = 0; mt < 2; mt++)
        #pragma unroll
        for (int j = 0; j < 8; j++)
            #pragma unroll
            for (int e = 0; e < 4; e++) acc[mt][j][e] = 0.f;

    const unsigned sA_hi = sb + 1024;
    const unsigned sA_lo = sA_hi + 16384;
    const unsigned sB_hi = sA_hi + 32768;
    const unsigned sB_lo = sA_hi + 49152;

    // per-thread ldmatrix base offsets (row part, constant across chunks)
    int arow[2], brow[8];
    #pragma unroll
    for (int mt = 0; mt < 2; mt++)
        arow[mt] = wm*32 + mt*16 + (lane & 7) + ((lane >> 3) & 1) * 8;
    #pragma unroll
    for (int j = 0; j < 8; j++)
        brow[j] = wn*64 + j*8 + (lane & 7);
    const int acolh = (lane >> 4) * 16;          // A k-halves by lane>=16
    const int bcolh = ((lane >> 3) & 1) * 16;    // B k-halves by lane bit 3

    for (int c = 0; c < NCHUNK; c++) {
        const int k0 = c * 64;
        __syncthreads();
        #pragma unroll
        for (int t = 0; t < 4; t++) {
            int i = tid + t * 256;
            int rr = i >> 3, q = i & 7;
            size_t ga = (size_t)(m0 + rr) * KDIM + k0 + q * 8;
            size_t gb = (size_t)(n0 + rr) * KDIM + k0 + q * 8;
            int so = rr * 128 + q * 16;
            int sw = so ^ ((so >> 3) & 0x70);
            *(uint4*)(smem + 1024 + sw)         = *(const uint4*)(Ahi + ga);
            *(uint4*)(smem + 1024 + 16384 + sw) = *(const uint4*)(Alo + ga);
            *(uint4*)(smem + 1024 + 32768 + sw) = *(const uint4*)(Bhi + gb);
            *(uint4*)(smem + 1024 + 49152 + sw) = *(const uint4*)(Blo + gb);
        }
        __syncthreads();

        #pragma unroll
        for (int ks = 0; ks < 4; ks++) {
            unsigned Ah[2][4], Al[2][4], Bh[8][2], Bl[8][2];
            #pragma unroll
            for (int mt = 0; mt < 2; mt++) {
                int off = arow[mt] * 128 + ks * 32 + acolh;
                off ^= (off >> 3) & 0x70;
                ldmx4(Ah[mt], sA_hi + off);
                ldmx4(Al[mt], sA_lo + off);
            }
            #pragma unroll
            for (int j = 0; j < 8; j++) {
                int off = brow[j] * 128 + ks * 32 + bcolh;
                off ^= (off >> 3) & 0x70;
                ldmx2(Bh[j], sB_hi + off);
                ldmx2(Bl[j], sB_lo + off);
            }
            #pragma unroll
            for (int mt = 0; mt < 2; mt++)
                #pragma unroll
                for (int j = 0; j < 8; j++) {
                    mma_bf16(acc[mt][j], Ah[mt], Bh[j]);
                    mma_bf16(acc[mt][j], Ah[mt], Bl[j]);
                    mma_bf16(acc[mt][j], Al[mt], Bh[j]);
                }
        }
    }

    // epilogue
    #pragma unroll
    for (int mt = 0; mt < 2; mt++) {
        int r0 = m0 + wm*32 + mt*16 + (lane >> 2);
        #pragma unroll
        for (int j = 0; j < 8; j++) {
            int col = n0 + wn*64 + j*8 + (lane & 3) * 2;
            float2 o0, o1;
            o0.x = acc[mt][j][0] + bias[col];
            o0.y = acc[mt][j][1] + bias[col + 1];
            o1.x = acc[mt][j][2] + bias[col];
            o1.y = acc[mt][j][3] + bias[col + 1];
            *(float2*)(C + (size_t)r0 * Ntot + col)       = o0;
            *(float2*)(C + (size_t)(r0 + 8) * Ntot + col) = o1;
        }
    }
#endif
}

// ---------------------------------------------------------------------------
// fp32 -> bf16 hi/lo split (elementwise)
// ---------------------------------------------------------------------------
__global__ void convert_split(const float* __restrict__ a,
                              __nv_bfloat16* __restrict__ hi,
                              __nv_bfloat16* __restrict__ lo)
{
    size_t i = ((size_t)blockIdx.x * blockDim.x + threadIdx.x) * 4;
    float4 v = *(const float4*)(a + i);
    __nv_bfloat16 h0 = __float2bfloat16(v.x);
    __nv_bfloat16 h1 = __float2bfloat16(v.y);
    __nv_bfloat16 h2 = __float2bfloat16(v.z);
    __nv_bfloat16 h3 = __float2bfloat16(v.w);
    __nv_bfloat16 l0 = __float2bfloat16(v.x - __bfloat162float(h0));
    __nv_bfloat16 l1 = __float2bfloat16(v.y - __bfloat162float(h1));
    __nv_bfloat16 l2 = __float2bfloat16(v.z - __bfloat162float(h2));
    __nv_bfloat16 l3 = __float2bfloat16(v.w - __bfloat162float(h3));
    __nv_bfloat162 ph0; ph0.x = h0; ph0.y = h1;
    __nv_bfloat162 ph1; ph1.x = h2; ph1.y = h3;
    __nv_bfloat162 pl0; pl0.x = l0; pl0.y = l1;
    __nv_bfloat162 pl1; pl1.x = l2; pl1.y = l3;
    *(__nv_bfloat162*)(hi + i)     = ph0;
    *(__nv_bfloat162*)(hi + i + 2) = ph1;
    *(__nv_bfloat162*)(lo + i)     = pl0;
    *(__nv_bfloat162*)(lo + i + 2) = pl1;
}

// ---------------------------------------------------------------------------
// weight transpose + split:  w[K,N] fp32  ->  hi/lo[N,K] bf16
// ---------------------------------------------------------------------------
__global__ void transpose_split(const float* __restrict__ w,
                                __nv_bfloat16* __restrict__ hi,
                                __nv_bfloat16* __restrict__ lo,
                                int K, int N)
{
    __shared__ float tile[32][33];
    const int k0 = blockIdx.x * 32, n0 = blockIdx.y * 32;
    const int tx = threadIdx.x, ty = threadIdx.y;   // 32 x 8
    #pragma unroll
    for (int i = 0; i < 32; i += 8)
        tile[ty + i][tx] = w[(size_t)(k0 + ty + i) * N + n0 + tx];
    __syncthreads();
    #pragma unroll
    for (int i = 0; i < 32; i += 8) {
        float v = tile[tx][ty + i];
        __nv_bfloat16 h = __float2bfloat16(v);
        size_t o = (size_t)(n0 + ty + i) * K + k0 + tx;
        hi[o] = h;
        lo[o] = __float2bfloat16(v - __bfloat162float(h));
    }
}

// ---------------------------------------------------------------------------
// RoPE
// ---------------------------------------------------------------------------
__global__ void rope_q_kernel(float* __restrict__ q)
{
    int idx = blockIdx.x * blockDim.x + threadIdx.x;
    int i = idx & 63;
    int s = (idx >> 10) & 2047;
    float inv = 1.0f / powf(10000.0f, (float)(2*i) * (1.0f/128.0f));
    float ang = (float)s * inv;
    float sn, cs;
    sincosf(ang, &sn, &cs);
    float2 v = *(float2*)(q + 2*(size_t)idx);
    float x1 = v.x, x2 = v.y;
    v.x = x1*cs - x2*sn;
    v.y = x1*sn + x2*cs;
    *(float2*)(q + 2*(size_t)idx) = v;
}

__global__ void rope_k_kernel(float* __restrict__ k, float* __restrict__ kh)
{
    int idx = blockIdx.x * blockDim.x + threadIdx.x;
    int i = idx & 63;
    int s = (idx >> 6) & 2047;
    float inv = 1.0f / powf(10000.0f, (float)(2*i) * (1.0f/128.0f));
    float ang = (float)s * inv;
    float sn, cs;
    sincosf(ang, &sn, &cs);
    float2 v = *(float2*)(k + 2*(size_t)idx);
    float x1 = v.x, x2 = v.y;
    v.x = x1*cs - x2*sn;
    v.y = x1*sn + x2*cs;
    *(float2*)(k + 2*(size_t)idx)  = v;
    *(float2*)(kh + 2*(size_t)idx) = v;
}

// ---------------------------------------------------------------------------
// Causal MQA flash attention (fp32) — unchanged.
// ---------------------------------------------------------------------------
#define ATT_SCALE 0.08838834764831845f

__global__ void __launch_bounds__(512) flash_attn(
    const float* __restrict__ Q, const float* __restrict__ K,
    const float* __restrict__ V, float* __restrict__ O)
{
    extern __shared__ float smbuf[];
    float* Qs = smbuf;              // 128*128
    float* Ks = Qs + 128*128;       // 64*132 (padded)
    float* Vs = Ks + 64*132;        // 64*128
    float* Ps = Vs + 64*128;        // 128*66 (padded)

    const int tid = threadIdx.x;
    const int tx = tid & 15, ty = tid >> 4;
    const int b = blockIdx.z, h = blockIdx.y;
    const int row0 = blockIdx.x * 128;

    #pragma unroll
    for (int it = 0; it < 8; it++) {
        int i = tid + it*512;
        int r = i >> 5, c = (i & 31) << 2;
        *(float4*)&Qs[r*128 + c] =
            *(const float4*)&Q[(((size_t)b*SEQ + row0 + r)*NH + h)*HD + c];
    }

    float m[4], l[4], o[4][8];
    #pragma unroll
    for (int rr = 0; rr < 4; rr++) {
        m[rr] = -INFINITY; l[rr] = 0.f;
        #pragma unroll
        for (int d = 0; d < 8; d++) o[rr][d] = 0.f;
    }

    const int n_tiles = 2*blockIdx.x + 2;
    for (int t = 0; t < n_tiles; t++) {
        const int kb = t * 64;
        __syncthreads();
        #pragma unroll
        for (int it = 0; it < 4; it++) {
            int i = tid + it*512;
            int r = i >> 5, c = (i & 31) << 2;
            size_t g = ((size_t)b*SEQ + kb + r)*HD + c;
            *(float4*)&Ks[r*132 + c] = *(const float4*)&K[g];
            *(float4*)&Vs[r*128 + c] = *(const float4*)&V[g];
        }
        __syncthreads();

        float s[4][4];
        #pragma unroll
        for (int rr = 0; rr < 4; rr++)
            #pragma unroll
            for (int jj = 0; jj < 4; jj++) s[rr][jj] = 0.f;

        #pragma unroll
        for (int dc = 0; dc < 32; dc++) {
            float4 a[4], kv[4];
            #pragma unroll
            for (int rr = 0; rr < 4; rr++)
                a[rr] = *(const float4*)&Qs[(ty + 32*rr)*128 + dc*4];
            #pragma unroll
            for (int jj = 0; jj < 4; jj++)
                kv[jj] = *(const float4*)&Ks[(tx + 16*jj)*132 + dc*4];
            #pragma unroll
            for (int rr = 0; rr < 4; rr++)
                #pragma unroll
                for (int jj = 0; jj < 4; jj++)
                    s[rr][jj] += a[rr].x*kv[jj].x + a[rr].y*kv[jj].y
                               + a[rr].z*kv[jj].z + a[rr].w*kv[jj].w;
        }

        #pragma unroll
        for (int rr = 0; rr < 4; rr++) {
            const int r = row0 + ty + 32*rr;
            float tmax = -INFINITY;
            #pragma unroll
            for (int jj = 0; jj < 4; jj++) {
                int j = kb + tx + 16*jj;
                float sv = (j <= r) ? s[rr][jj]*ATT_SCALE : -INFINITY;
                s[rr][jj] = sv;
                tmax = fmaxf(tmax, sv);
            }
            #pragma unroll
            for (int off = 8; off; off >>= 1)
                tmax = fmaxf(tmax, __shfl_xor_sync(0xffffffffu, tmax, off, 16));
            float mn = fmaxf(m[rr], tmax);
            float rsum = 0.f;
            #pragma unroll
            for (int jj = 0; jj < 4; jj++) {
                float p = __expf(s[rr][jj] - mn);
                s[rr][jj] = p;
                rsum += p;
            }
            #pragma unroll
            for (int off = 8; off; off >>= 1)
                rsum += __shfl_xor_sync(0xffffffffu, rsum, off, 16);
            float alpha = __expf(m[rr] - mn);
            m[rr] = mn;
            l[rr] = l[rr]*alpha + rsum;
            #pragma unroll
            for (int d = 0; d < 8; d++) o[rr][d] *= alpha;
            #pragma unroll
            for (int jj = 0; jj < 4; jj++)
                Ps[(ty + 32*rr)*66 + tx + 16*jj] = s[rr][jj];
        }
        __syncthreads();

        #pragma unroll 4
        for (int j = 0; j < 64; j++) {
            float4 v0 = *(const float4*)&Vs[j*128 + tx*4];
            float4 v1 = *(const float4*)&Vs[j*128 + tx*4 + 64];
            #pragma unroll
            for (int rr = 0; rr < 4; rr++) {
                float p = Ps[(ty + 32*rr)*66 + j];
                o[rr][0] += p*v0.x; o[rr][1] += p*v0.y;
                o[rr][2] += p*v0.z; o[rr][3] += p*v0.w;
                o[rr][4] += p*v1.x; o[rr][5] += p*v1.y;
                o[rr][6] += p*v1.z; o[rr][7] += p*v1.w;
            }
        }
    }

    #pragma unroll
    for (int rr = 0; rr < 4; rr++) {
        float inv = 1.0f / l[rr];
        size_t base = (((size_t)b*SEQ + row0 + ty + 32*rr)*NH + h)*HD;
        float4 w0 = make_float4(o[rr][0]*inv, o[rr][1]*inv, o[rr][2]*inv, o[rr][3]*inv);
        float4 w1 = make_float4(o[rr][4]*inv, o[rr][5]*inv, o[rr][6]*inv, o[rr][7]*inv);
        *(float4*)&O[base + tx*4]      = w0;
        *(float4*)&O[base + tx*4 + 64] = w1;
    }
}

// ---------------------------------------------------------------------------
extern "C" void kernel_launch(void* const* d_in, const int* in_sizes, int n_in,
                              void* d_out, int out_size)
{
    const float* x  = (const float*)d_in[0];
    const float* wq = (const float*)d_in[1];
    const float* bq = (const float*)d_in[2];
    const float* wk = (const float*)d_in[3];
    const float* bk = (const float*)d_in[4];
    const float* wv = (const float*)d_in[5];
    const float* bv = (const float*)d_in[6];
    const float* wo = (const float*)d_in[7];
    const float* bo = (const float*)d_in[8];

    float* out = (float*)d_out;                      // (B,S,D)
    float* kh  = out + (size_t)MROWS*DM;             // (B,1,S,HD)
    float* vh  = kh  + (size_t)MROWS*HD;             // (B,1,S,HD)

    float *qp, *kp, *ap;
    cudaGetSymbolAddress((void**)&qp, g_q);
    cudaGetSymbolAddress((void**)&kp, g_k);
    cudaGetSymbolAddress((void**)&ap, g_attn);
    __nv_bfloat16 *ahi, *alo, *wqh, *wql, *wkh, *wkl, *wvh, *wvl, *woh, *wol;
    cudaGetSymbolAddress((void**)&ahi, g_ahi);
    cudaGetSymbolAddress((void**)&alo, g_alo);
    cudaGetSymbolAddress((void**)&wqh, g_wqT_hi);
    cudaGetSymbolAddress((void**)&wql, g_wqT_lo);
    cudaGetSymbolAddress((void**)&wkh, g_wkT_hi);
    cudaGetSymbolAddress((void**)&wkl, g_wkT_lo);
    cudaGetSymbolAddress((void**)&wvh, g_wvT_hi);
    cudaGetSymbolAddress((void**)&wvl, g_wvT_lo);
    cudaGetSymbolAddress((void**)&woh, g_woT_hi);
    cudaGetSymbolAddress((void**)&wol, g_woT_lo);

    const int GEMM_SMEM  = 1024 + 2*65536;  // 132,096 B (tcgen05 path uses both bufs)
    const int FLASH_SMEM = (128*128 + 64*132 + 64*128 + 128*66) * 4; // 165,888 B
    cudaFuncSetAttribute(gemm_tc, cudaFuncAttributeMaxDynamicSharedMemorySize,
                         GEMM_SMEM);
    cudaFuncSetAttribute(flash_attn, cudaFuncAttributeMaxDynamicSharedMemorySize,
                         FLASH_SMEM);

    // split activations and weights to bf16 hi/lo
    convert_split<<<(size_t)MROWS*DM/1024, 256>>>(x, ahi, alo);
    transpose_split<<<dim3(DM/32, DM/32), dim3(32,8)>>>(wq, wqh, wql, DM, DM);
    transpose_split<<<dim3(DM/32, HD/32), dim3(32,8)>>>(wk, wkh, wkl, DM, HD);
    transpose_split<<<dim3(DM/32, HD/32), dim3(32,8)>>>(wv, wvh, wvl, DM, HD);
    transpose_split<<<dim3(DM/32, DM/32), dim3(32,8)>>>(wo, woh, wol, DM, DM);

    // projections (tensor cores, bf16x3)
    gemm_tc<<<dim3(DM/128, MROWS/128), 256, GEMM_SMEM>>>(ahi, alo, wqh, wql, bq, qp, DM);
    gemm_tc<<<dim3(1,      MROWS/128), 256, GEMM_SMEM>>>(ahi, alo, wkh, wkl, bk, kp, HD);
    gemm_tc<<<dim3(1,      MROWS/128), 256, GEMM_SMEM>>>(ahi, alo, wvh, wvl, bv, vh, HD);

    // rope
    rope_q_kernel<<<(MROWS*NH*64)/256, 256>>>(qp);
    rope_k_kernel<<<(MROWS*64)/256, 256>>>(kp, kh);

    // attention (fp32)
    flash_attn<<<dim3(16, 16, 4), 512, FLASH_SMEM>>>(qp, kp, vh, ap);

    // output projection
    convert_split<<<(size_t)MROWS*DM/1024, 256>>>(ap, ahi, alo);
    gemm_tc<<<dim3(DM/128, MROWS/128), 256, GEMM_SMEM>>>(ahi, alo, woh, wol, bo, out, DM);
}

// round 4
// speedup vs baseline: 2.1085x; 1.3184x over previous
#include <cuda_runtime.h>
#include <cuda_bf16.h>
#include <math.h>

#define BATCH 4
#define SEQ   2048
#define NH    16
#define HD    128
#define DM    2048
#define MROWS (BATCH*SEQ)
#define KDIM  2048
#define NCHUNK (KDIM/64)

// ---------------------------------------------------------------------------
// scratch (device globals; no cudaMalloc anywhere)
// ---------------------------------------------------------------------------
__device__ float g_q[(size_t)MROWS*DM];     // q projection fp32 (pre-rope)
__device__ float g_k[(size_t)MROWS*HD];     // k projection fp32 (pre-rope)
__device__ float g_attn[(size_t)MROWS*DM];  // attention output fp32
__device__ __nv_bfloat16 g_ahi[(size_t)MROWS*DM];   // split activations
__device__ __nv_bfloat16 g_alo[(size_t)MROWS*DM];
__device__ __nv_bfloat16 g_wqT_hi[(size_t)DM*DM], g_wqT_lo[(size_t)DM*DM];
__device__ __nv_bfloat16 g_woT_hi[(size_t)DM*DM], g_woT_lo[(size_t)DM*DM];
__device__ __nv_bfloat16 g_wkT_hi[(size_t)HD*DM], g_wkT_lo[(size_t)HD*DM];
__device__ __nv_bfloat16 g_wvT_hi[(size_t)HD*DM], g_wvT_lo[(size_t)HD*DM];
// attention operands (bf16 hi/lo)
__device__ __nv_bfloat16 g_qhi[(size_t)MROWS*DM],  g_qlo[(size_t)MROWS*DM];   // [B,S,NH,HD]
__device__ __nv_bfloat16 g_khi[(size_t)MROWS*HD],  g_klo[(size_t)MROWS*HD];   // [B,S,HD]
__device__ __nv_bfloat16 g_vthi[(size_t)MROWS*HD], g_vtlo[(size_t)MROWS*HD];  // [B,HD,S]

// ---------------------------------------------------------------------------
// helpers
// ---------------------------------------------------------------------------
__device__ __forceinline__ unsigned s2u(const void* p) {
    unsigned a;
    asm("{ .reg .u64 t; cvta.to.shared.u64 t, %1; cvt.u32.u64 %0, t; }"
        : "=r"(a) : "l"(p));
    return a;
}
__device__ __forceinline__ void ldmx4(unsigned r[4], unsigned addr) {
    asm volatile("ldmatrix.sync.aligned.m8n8.x4.shared.b16 {%0,%1,%2,%3}, [%4];"
                 : "=r"(r[0]), "=r"(r[1]), "=r"(r[2]), "=r"(r[3]) : "r"(addr));
}
__device__ __forceinline__ void ldmx2(unsigned r[2], unsigned addr) {
    asm volatile("ldmatrix.sync.aligned.m8n8.x2.shared.b16 {%0,%1}, [%2];"
                 : "=r"(r[0]), "=r"(r[1]) : "r"(addr));
}
__device__ __forceinline__ void mma_bf16(float c[4], const unsigned a[4],
                                         const unsigned b[2]) {
    asm volatile(
        "mma.sync.aligned.m16n8k16.row.col.f32.bf16.bf16.f32 "
        "{%0,%1,%2,%3}, {%4,%5,%6,%7}, {%8,%9}, {%0,%1,%2,%3};"
        : "+f"(c[0]), "+f"(c[1]), "+f"(c[2]), "+f"(c[3])
        : "r"(a[0]), "r"(a[1]), "r"(a[2]), "r"(a[3]), "r"(b[0]), "r"(b[1]));
}
__device__ __forceinline__ unsigned pack_bf16(float a, float b) {
    __nv_bfloat162 t = __floats2bfloat162_rn(a, b);
    return *(unsigned*)&t;
}

// ---------------------------------------------------------------------------
// bf16x3 GEMM (mma.sync):  C[M,Ntot] = (Ahi+Alo)[M,K] @ (Bhi+Blo)[Ntot,K]^T + bias
// BM=BN=128, BK=64 (SW128 smem), 256 threads.
// ---------------------------------------------------------------------------
__global__ void __launch_bounds__(256) gemm_tc(
    const __nv_bfloat16* __restrict__ Ahi, const __nv_bfloat16* __restrict__ Alo,
    const __nv_bfloat16* __restrict__ Bhi, const __nv_bfloat16* __restrict__ Blo,
    const float* __restrict__ bias, float* __restrict__ C, int Ntot)
{
    extern __shared__ __align__(1024) char smem[];
    const unsigned sb = s2u(smem);
    const int tid = threadIdx.x;
    const int m0 = blockIdx.y * 128;
    const int n0 = blockIdx.x * 128;

    const int lane = tid & 31, w = tid >> 5;
    const int wm = w & 3, wn = w >> 2;        // warp tile: 32 (M) x 64 (N)

    float acc[2][8][4];
    #pragma unroll
    for (int mt = 0; mt < 2; mt++)
        #pragma unroll
        for (int j = 0; j < 8; j++)
            #pragma unroll
            for (int e = 0; e < 4; e++) acc[mt][j][e] = 0.f;

    const unsigned sA_hi = sb + 1024;
    const unsigned sA_lo = sA_hi + 16384;
    const unsigned sB_hi = sA_hi + 32768;
    const unsigned sB_lo = sA_hi + 49152;

    int arow[2], brow[8];
    #pragma unroll
    for (int mt = 0; mt < 2; mt++)
        arow[mt] = wm*32 + mt*16 + (lane & 7) + ((lane >> 3) & 1) * 8;
    #pragma unroll
    for (int j = 0; j < 8; j++)
        brow[j] = wn*64 + j*8 + (lane & 7);
    const int acolh = (lane >> 4) * 16;
    const int bcolh = ((lane >> 3) & 1) * 16;

    for (int c = 0; c < NCHUNK; c++) {
        const int k0 = c * 64;
        __syncthreads();
        #pragma unroll
        for (int t = 0; t < 4; t++) {
            int i = tid + t * 256;
            int rr = i >> 3, q = i & 7;
            size_t ga = (size_t)(m0 + rr) * KDIM + k0 + q * 8;
            size_t gb = (size_t)(n0 + rr) * KDIM + k0 + q * 8;
            int so = rr * 128 + q * 16;
            int sw = so ^ ((so >> 3) & 0x70);
            *(uint4*)(smem + 1024 + sw)         = *(const uint4*)(Ahi + ga);
            *(uint4*)(smem + 1024 + 16384 + sw) = *(const uint4*)(Alo + ga);
            *(uint4*)(smem + 1024 + 32768 + sw) = *(const uint4*)(Bhi + gb);
            *(uint4*)(smem + 1024 + 49152 + sw) = *(const uint4*)(Blo + gb);
        }
        __syncthreads();

        #pragma unroll
        for (int ks = 0; ks < 4; ks++) {
            unsigned Ah[2][4], Al[2][4], Bh[8][2], Bl[8][2];
            #pragma unroll
            for (int mt = 0; mt < 2; mt++) {
                int off = arow[mt] * 128 + ks * 32 + acolh;
                off ^= (off >> 3) & 0x70;
                ldmx4(Ah[mt], sA_hi + off);
                ldmx4(Al[mt], sA_lo + off);
            }
            #pragma unroll
            for (int j = 0; j < 8; j++) {
                int off = brow[j] * 128 + ks * 32 + bcolh;
                off ^= (off >> 3) & 0x70;
                ldmx2(Bh[j], sB_hi + off);
                ldmx2(Bl[j], sB_lo + off);
            }
            #pragma unroll
            for (int mt = 0; mt < 2; mt++)
                #pragma unroll
                for (int j = 0; j < 8; j++) {
                    mma_bf16(acc[mt][j], Ah[mt], Bh[j]);
                    mma_bf16(acc[mt][j], Ah[mt], Bl[j]);
                    mma_bf16(acc[mt][j], Al[mt], Bh[j]);
                }
        }
    }

    #pragma unroll
    for (int mt = 0; mt < 2; mt++) {
        int r0 = m0 + wm*32 + mt*16 + (lane >> 2);
        #pragma unroll
        for (int j = 0; j < 8; j++) {
            int col = n0 + wn*64 + j*8 + (lane & 3) * 2;
            float2 o0, o1;
            o0.x = acc[mt][j][0] + bias[col];
            o0.y = acc[mt][j][1] + bias[col + 1];
            o1.x = acc[mt][j][2] + bias[col];
            o1.y = acc[mt][j][3] + bias[col + 1];
            *(float2*)(C + (size_t)r0 * Ntot + col)       = o0;
            *(float2*)(C + (size_t)(r0 + 8) * Ntot + col) = o1;
        }
    }
}

// ---------------------------------------------------------------------------
// fp32 -> bf16 hi/lo split (elementwise)
// ---------------------------------------------------------------------------
__global__ void convert_split(const float* __restrict__ a,
                              __nv_bfloat16* __restrict__ hi,
                              __nv_bfloat16* __restrict__ lo)
{
    size_t i = ((size_t)blockIdx.x * blockDim.x + threadIdx.x) * 4;
    float4 v = *(const float4*)(a + i);
    __nv_bfloat16 h0 = __float2bfloat16(v.x);
    __nv_bfloat16 h1 = __float2bfloat16(v.y);
    __nv_bfloat16 h2 = __float2bfloat16(v.z);
    __nv_bfloat16 h3 = __float2bfloat16(v.w);
    __nv_bfloat16 l0 = __float2bfloat16(v.x - __bfloat162float(h0));
    __nv_bfloat16 l1 = __float2bfloat16(v.y - __bfloat162float(h1));
    __nv_bfloat16 l2 = __float2bfloat16(v.z - __bfloat162float(h2));
    __nv_bfloat16 l3 = __float2bfloat16(v.w - __bfloat162float(h3));
    __nv_bfloat162 ph0; ph0.x = h0; ph0.y = h1;
    __nv_bfloat162 ph1; ph1.x = h2; ph1.y = h3;
    __nv_bfloat162 pl0; pl0.x = l0; pl0.y = l1;
    __nv_bfloat162 pl1; pl1.x = l2; pl1.y = l3;
    *(__nv_bfloat162*)(hi + i)     = ph0;
    *(__nv_bfloat162*)(hi + i + 2) = ph1;
    *(__nv_bfloat162*)(lo + i)     = pl0;
    *(__nv_bfloat162*)(lo + i + 2) = pl1;
}

// ---------------------------------------------------------------------------
// weight transpose + split:  w[K,N] fp32  ->  hi/lo[N,K] bf16
// ---------------------------------------------------------------------------
__global__ void transpose_split(const float* __restrict__ w,
                                __nv_bfloat16* __restrict__ hi,
                                __nv_bfloat16* __restrict__ lo,
                                int K, int N)
{
    __shared__ float tile[32][33];
    const int k0 = blockIdx.x * 32, n0 = blockIdx.y * 32;
    const int tx = threadIdx.x, ty = threadIdx.y;   // 32 x 8
    #pragma unroll
    for (int i = 0; i < 32; i += 8)
        tile[ty + i][tx] = w[(size_t)(k0 + ty + i) * N + n0 + tx];
    __syncthreads();
    #pragma unroll
    for (int i = 0; i < 32; i += 8) {
        float v = tile[tx][ty + i];
        __nv_bfloat16 h = __float2bfloat16(v);
        size_t o = (size_t)(n0 + ty + i) * K + k0 + tx;
        hi[o] = h;
        lo[o] = __float2bfloat16(v - __bfloat162float(h));
    }
}

// ---------------------------------------------------------------------------
// V transpose + split:  vh[B,S,HD] fp32 -> vthi/vtlo[B,HD,S] bf16
// ---------------------------------------------------------------------------
__global__ void vt_split(const float* __restrict__ v,
                         __nv_bfloat16* __restrict__ hi,
                         __nv_bfloat16* __restrict__ lo)
{
    __shared__ float tile[32][33];
    const int s0 = blockIdx.x * 32, h0 = blockIdx.y * 32, b = blockIdx.z;
    const int tx = threadIdx.x, ty = threadIdx.y;   // 32 x 8
    #pragma unroll
    for (int i = 0; i < 32; i += 8)
        tile[ty + i][tx] = v[((size_t)b*SEQ + s0 + ty + i) * HD + h0 + tx];
    __syncthreads();
    #pragma unroll
    for (int i = 0; i < 32; i += 8) {
        float val = tile[tx][ty + i];   // row s0+tx, col h0+ty+i
        __nv_bfloat16 h = __float2bfloat16(val);
        size_t o = ((size_t)b*HD + h0 + ty + i) * SEQ + s0 + tx;
        hi[o] = h;
        lo[o] = __float2bfloat16(val - __bfloat162float(h));
    }
}

// ---------------------------------------------------------------------------
// RoPE (fp32 in, bf16 hi/lo out)
// ---------------------------------------------------------------------------
__global__ void rope_q_split(const float* __restrict__ q,
                             __nv_bfloat16* __restrict__ qhi,
                             __nv_bfloat16* __restrict__ qlo)
{
    int idx = blockIdx.x * blockDim.x + threadIdx.x;   // over B*S*H*64 pairs
    int i = idx & 63;
    int s = (idx >> 10) & 2047;
    float inv = 1.0f / powf(10000.0f, (float)(2*i) * (1.0f/128.0f));
    float ang = (float)s * inv;
    float sn, cs;
    sincosf(ang, &sn, &cs);
    float2 v = *(const float2*)(q + 2*(size_t)idx);
    float o1 = v.x*cs - v.y*sn;
    float o2 = v.x*sn + v.y*cs;
    __nv_bfloat162 h = __floats2bfloat162_rn(o1, o2);
    __nv_bfloat162 l = __floats2bfloat162_rn(o1 - __bfloat162float(h.x),
                                             o2 - __bfloat162float(h.y));
    *(__nv_bfloat162*)(qhi + 2*(size_t)idx) = h;
    *(__nv_bfloat162*)(qlo + 2*(size_t)idx) = l;
}

__global__ void rope_k_split(const float* __restrict__ k, float* __restrict__ kh,
                             __nv_bfloat16* __restrict__ khi,
                             __nv_bfloat16* __restrict__ klo)
{
    int idx = blockIdx.x * blockDim.x + threadIdx.x;   // over B*S*64 pairs
    int i = idx & 63;
    int s = (idx >> 6) & 2047;
    float inv = 1.0f / powf(10000.0f, (float)(2*i) * (1.0f/128.0f));
    float ang = (float)s * inv;
    float sn, cs;
    sincosf(ang, &sn, &cs);
    float2 v = *(const float2*)(k + 2*(size_t)idx);
    float o1 = v.x*cs - v.y*sn;
    float o2 = v.x*sn + v.y*cs;
    float2 of; of.x = o1; of.y = o2;
    *(float2*)(kh + 2*(size_t)idx) = of;
    __nv_bfloat162 h = __floats2bfloat162_rn(o1, o2);
    __nv_bfloat162 l = __floats2bfloat162_rn(o1 - __bfloat162float(h.x),
                                             o2 - __bfloat162float(h.y));
    *(__nv_bfloat162*)(khi + 2*(size_t)idx) = h;
    *(__nv_bfloat162*)(klo + 2*(size_t)idx) = l;
}

// ---------------------------------------------------------------------------
// Tensor-core causal MQA flash attention (bf16x3, fp32 softmax).
// CTA: 128 q-rows x (64-kv tiles), 8 warps, warp = 16 q-rows.
// ---------------------------------------------------------------------------
#define ATT_SCALE 0.08838834764831845f
#define PQ  136   // smem pitch for Q/K tiles (bf16)
#define PVT 72    // smem pitch for Vt tiles (bf16)

__global__ void __launch_bounds__(256) flash_tc(
    const __nv_bfloat16* __restrict__ Qhi, const __nv_bfloat16* __restrict__ Qlo,
    const __nv_bfloat16* __restrict__ Khi, const __nv_bfloat16* __restrict__ Klo,
    const __nv_bfloat16* __restrict__ Vthi, const __nv_bfloat16* __restrict__ Vtlo,
    float* __restrict__ O)
{
    extern __shared__ __align__(16) __nv_bfloat16 sm[];
    __nv_bfloat16* QH = sm;                    // 128 x PQ
    __nv_bfloat16* QL = QH + 128*PQ;
    __nv_bfloat16* KH = QL + 128*PQ;           // 64 x PQ
    __nv_bfloat16* KL = KH + 64*PQ;
    __nv_bfloat16* VH = KL + 64*PQ;            // 128 x PVT (Vt: hd rows, kv cols)
    __nv_bfloat16* VL = VH + 128*PVT;

    const int tid = threadIdx.x;
    const int lane = tid & 31, w = tid >> 5;
    const int b = blockIdx.z, h = blockIdx.y;
    const int row0 = blockIdx.x * 128;

    // stage Q (hi/lo)
    #pragma unroll
    for (int t = 0; t < 8; t++) {
        int u = tid + t*256;
        int r = u >> 4, c = (u & 15) * 8;
        size_t g = (((size_t)b*SEQ + row0 + r)*NH + h)*HD + c;
        *(uint4*)&QH[r*PQ + c] = *(const uint4*)&Qhi[g];
        *(uint4*)&QL[r*PQ + c] = *(const uint4*)&Qlo[g];
    }
    __syncthreads();

    // Q fragments in registers (warp rows [w*16, w*16+16))
    unsigned qh[8][4], ql[8][4];
    {
        const int ar = w*16 + (lane & 7) + ((lane >> 3) & 1) * 8;
        const int ac = (lane >> 4) * 8;
        #pragma unroll
        for (int kt = 0; kt < 8; kt++) {
            ldmx4(qh[kt], s2u(&QH[ar*PQ + kt*16 + ac]));
            ldmx4(ql[kt], s2u(&QL[ar*PQ + kt*16 + ac]));
        }
    }

    float m0 = -INFINITY, m1 = -INFINITY, l0 = 0.f, l1 = 0.f;
    float o[16][4];
    #pragma unroll
    for (int n = 0; n < 16; n++)
        #pragma unroll
        for (int e = 0; e < 4; e++) o[n][e] = 0.f;

    const int qr0 = row0 + w*16 + (lane >> 2);
    const int qr1 = qr0 + 8;
    const int kcol = 2*(lane & 3);
    const int krow = lane & 7;
    const int kchalf = ((lane >> 3) & 1) * 8;

    const int n_tiles = 2*blockIdx.x + 2;
    for (int t = 0; t < n_tiles; t++) {
        const int kb = t*64;
        __syncthreads();   // previous iteration's consumers done
        #pragma unroll
        for (int tt = 0; tt < 4; tt++) {
            int u = tid + tt*256;
            {
                int r = u >> 4, c = (u & 15)*8;
                size_t g = ((size_t)b*SEQ + kb + r)*HD + c;
                *(uint4*)&KH[r*PQ + c] = *(const uint4*)&Khi[g];
                *(uint4*)&KL[r*PQ + c] = *(const uint4*)&Klo[g];
            }
            {
                int r = u >> 3, c = (u & 7)*8;
                size_t g = ((size_t)b*HD + r)*SEQ + kb + c;
                *(uint4*)&VH[r*PVT + c] = *(const uint4*)&Vthi[g];
                *(uint4*)&VL[r*PVT + c] = *(const uint4*)&Vtlo[g];
            }
        }
        __syncthreads();

        // S = Q K^T  (bf16x3)
        float s[8][4];
        #pragma unroll
        for (int j = 0; j < 8; j++)
            #pragma unroll
            for (int e = 0; e < 4; e++) s[j][e] = 0.f;

        #pragma unroll
        for (int kt = 0; kt < 8; kt++) {
            #pragma unroll
            for (int j = 0; j < 8; j++) {
                unsigned bh2[2], bl2[2];
                int off = (j*8 + krow)*PQ + kt*16 + kchalf;
                ldmx2(bh2, s2u(&KH[off]));
                ldmx2(bl2, s2u(&KL[off]));
                mma_bf16(s[j], qh[kt], bh2);
                mma_bf16(s[j], qh[kt], bl2);
                mma_bf16(s[j], ql[kt], bh2);
            }
        }

        // causal mask + scale + row max
        float tm0 = -INFINITY, tm1 = -INFINITY;
        #pragma unroll
        for (int j = 0; j < 8; j++) {
            int c0 = kb + j*8 + kcol;
            s[j][0] = (c0     <= qr0) ? s[j][0]*ATT_SCALE : -INFINITY;
            s[j][1] = (c0 + 1 <= qr0) ? s[j][1]*ATT_SCALE : -INFINITY;
            s[j][2] = (c0     <= qr1) ? s[j][2]*ATT_SCALE : -INFINITY;
            s[j][3] = (c0 + 1 <= qr1) ? s[j][3]*ATT_SCALE : -INFINITY;
            tm0 = fmaxf(tm0, fmaxf(s[j][0], s[j][1]));
            tm1 = fmaxf(tm1, fmaxf(s[j][2], s[j][3]));
        }
        tm0 = fmaxf(tm0, __shfl_xor_sync(0xffffffffu, tm0, 1));
        tm0 = fmaxf(tm0, __shfl_xor_sync(0xffffffffu, tm0, 2));
        tm1 = fmaxf(tm1, __shfl_xor_sync(0xffffffffu, tm1, 1));
        tm1 = fmaxf(tm1, __shfl_xor_sync(0xffffffffu, tm1, 2));

        float mn0 = fmaxf(m0, tm0), mn1 = fmaxf(m1, tm1);
        float rs0 = 0.f, rs1 = 0.f;
        unsigned pH[8][2], pL[8][2];
        #pragma unroll
        for (int j = 0; j < 8; j++) {
            float p0 = __expf(s[j][0] - mn0), p1 = __expf(s[j][1] - mn0);
            float p2 = __expf(s[j][2] - mn1), p3 = __expf(s[j][3] - mn1);
            rs0 += p0 + p1; rs1 += p2 + p3;
            __nv_bfloat162 h01 = __floats2bfloat162_rn(p0, p1);
            __nv_bfloat162 h23 = __floats2bfloat162_rn(p2, p3);
            pH[j][0] = *(unsigned*)&h01;
            pH[j][1] = *(unsigned*)&h23;
            pL[j][0] = pack_bf16(p0 - __bfloat162float(h01.x),
                                 p1 - __bfloat162float(h01.y));
            pL[j][1] = pack_bf16(p2 - __bfloat162float(h23.x),
                                 p3 - __bfloat162float(h23.y));
        }
        rs0 += __shfl_xor_sync(0xffffffffu, rs0, 1);
        rs0 += __shfl_xor_sync(0xffffffffu, rs0, 2);
        rs1 += __shfl_xor_sync(0xffffffffu, rs1, 1);
        rs1 += __shfl_xor_sync(0xffffffffu, rs1, 2);

        float al0 = __expf(m0 - mn0), al1 = __expf(m1 - mn1);
        m0 = mn0; m1 = mn1;
        l0 = l0*al0 + rs0; l1 = l1*al1 + rs1;
        #pragma unroll
        for (int n = 0; n < 16; n++) {
            o[n][0] *= al0; o[n][1] *= al0;
            o[n][2] *= al1; o[n][3] *= al1;
        }

        // O += P V  (bf16x3; P fragments straight from registers)
        #pragma unroll
        for (int ks = 0; ks < 4; ks++) {
            unsigned aH[4] = {pH[2*ks][0], pH[2*ks][1], pH[2*ks+1][0], pH[2*ks+1][1]};
            unsigned aL[4] = {pL[2*ks][0], pL[2*ks][1], pL[2*ks+1][0], pL[2*ks+1][1]};
            #pragma unroll
            for (int n = 0; n < 16; n++) {
                unsigned vh2[2], vl2[2];
                int off = (n*8 + krow)*PVT + ks*16 + kchalf;
                ldmx2(vh2, s2u(&VH[off]));
                ldmx2(vl2, s2u(&VL[off]));
                mma_bf16(o[n], aH, vh2);
                mma_bf16(o[n], aH, vl2);
                mma_bf16(o[n], aL, vh2);
            }
        }
    }

    // epilogue
    const float i0 = 1.f / l0, i1 = 1.f / l1;
    #pragma unroll
    for (int n = 0; n < 16; n++) {
        int col = n*8 + kcol;
        size_t g0 = (((size_t)b*SEQ + qr0)*NH + h)*HD + col;
        size_t g1 = (((size_t)b*SEQ + qr1)*NH + h)*HD + col;
        float2 w0; w0.x = o[n][0]*i0; w0.y = o[n][1]*i0;
        float2 w1; w1.x = o[n][2]*i1; w1.y = o[n][3]*i1;
        *(float2*)&O[g0] = w0;
        *(float2*)&O[g1] = w1;
    }
}

// ---------------------------------------------------------------------------
extern "C" void kernel_launch(void* const* d_in, const int* in_sizes, int n_in,
                              void* d_out, int out_size)
{
    const float* x  = (const float*)d_in[0];
    const float* wq = (const float*)d_in[1];
    const float* bq = (const float*)d_in[2];
    const float* wk = (const float*)d_in[3];
    const float* bk = (const float*)d_in[4];
    const float* wv = (const float*)d_in[5];
    const float* bv = (const float*)d_in[6];
    const float* wo = (const float*)d_in[7];
    const float* bo = (const float*)d_in[8];

    float* out = (float*)d_out;                      // (B,S,D)
    float* kh  = out + (size_t)MROWS*DM;             // (B,1,S,HD)
    float* vh  = kh  + (size_t)MROWS*HD;             // (B,1,S,HD)

    float *qp, *kp, *ap;
    cudaGetSymbolAddress((void**)&qp, g_q);
    cudaGetSymbolAddress((void**)&kp, g_k);
    cudaGetSymbolAddress((void**)&ap, g_attn);
    __nv_bfloat16 *ahi, *alo, *wqh, *wql, *wkh, *wkl, *wvh, *wvl, *woh, *wol;
    __nv_bfloat16 *qhi, *qlo, *khi, *klo, *vthi, *vtlo;
    cudaGetSymbolAddress((void**)&ahi, g_ahi);
    cudaGetSymbolAddress((void**)&alo, g_alo);
    cudaGetSymbolAddress((void**)&wqh, g_wqT_hi);
    cudaGetSymbolAddress((void**)&wql, g_wqT_lo);
    cudaGetSymbolAddress((void**)&wkh, g_wkT_hi);
    cudaGetSymbolAddress((void**)&wkl, g_wkT_lo);
    cudaGetSymbolAddress((void**)&wvh, g_wvT_hi);
    cudaGetSymbolAddress((void**)&wvl, g_wvT_lo);
    cudaGetSymbolAddress((void**)&woh, g_woT_hi);
    cudaGetSymbolAddress((void**)&wol, g_woT_lo);
    cudaGetSymbolAddress((void**)&qhi, g_qhi);
    cudaGetSymbolAddress((void**)&qlo, g_qlo);
    cudaGetSymbolAddress((void**)&khi, g_khi);
    cudaGetSymbolAddress((void**)&klo, g_klo);
    cudaGetSymbolAddress((void**)&vthi, g_vthi);
    cudaGetSymbolAddress((void**)&vtlo, g_vtlo);

    const int GEMM_SMEM  = 1024 + 65536;
    const int FLASH_SMEM = (2*128*PQ + 2*64*PQ + 2*128*PVT) * 2;  // 141,312 B
    cudaFuncSetAttribute(gemm_tc, cudaFuncAttributeMaxDynamicSharedMemorySize,
                         GEMM_SMEM);
    cudaFuncSetAttribute(flash_tc, cudaFuncAttributeMaxDynamicSharedMemorySize,
                         FLASH_SMEM);

    // split activations and weights to bf16 hi/lo
    convert_split<<<(size_t)MROWS*DM/1024, 256>>>(x, ahi, alo);
    transpose_split<<<dim3(DM/32, DM/32), dim3(32,8)>>>(wq, wqh, wql, DM, DM);
    transpose_split<<<dim3(DM/32, HD/32), dim3(32,8)>>>(wk, wkh, wkl, DM, HD);
    transpose_split<<<dim3(DM/32, HD/32), dim3(32,8)>>>(wv, wvh, wvl, DM, HD);
    transpose_split<<<dim3(DM/32, DM/32), dim3(32,8)>>>(wo, woh, wol, DM, DM);

    // projections (tensor cores, bf16x3)
    gemm_tc<<<dim3(DM/128, MROWS/128), 256, GEMM_SMEM>>>(ahi, alo, wqh, wql, bq, qp, DM);
    gemm_tc<<<dim3(1,      MROWS/128), 256, GEMM_SMEM>>>(ahi, alo, wkh, wkl, bk, kp, HD);
    gemm_tc<<<dim3(1,      MROWS/128), 256, GEMM_SMEM>>>(ahi, alo, wvh, wvl, bv, vh, HD);

    // rope + attention operand prep
    rope_q_split<<<(MROWS*NH*64)/256, 256>>>(qp, qhi, qlo);
    rope_k_split<<<(MROWS*64)/256, 256>>>(kp, kh, khi, klo);
    vt_split<<<dim3(SEQ/32, HD/32, BATCH), dim3(32,8)>>>(vh, vthi, vtlo);

    // attention (tensor cores, bf16x3)
    flash_tc<<<dim3(16, 16, 4), 256, FLASH_SMEM>>>(qhi, qlo, khi, klo, vthi, vtlo, ap);

    // output projection
    convert_split<<<(size_t)MROWS*DM/1024, 256>>>(ap, ahi, alo);
    gemm_tc<<<dim3(DM/128, MROWS/128), 256, GEMM_SMEM>>>(ahi, alo, woh, wol, bo, out, DM);
}

// round 5
// speedup vs baseline: 2.9372x; 1.3931x over previous
#include <cuda_runtime.h>
#include <cuda_bf16.h>
#include <math.h>

#define BATCH 4
#define SEQ   2048
#define NH    16
#define HD    128
#define DM    2048
#define MROWS (BATCH*SEQ)
#define KDIM  2048
#define NCHUNK (KDIM/64)

// ---------------------------------------------------------------------------
// scratch (device globals; no cudaMalloc anywhere)
// ---------------------------------------------------------------------------
__device__ float g_q[(size_t)MROWS*DM];     // q projection fp32 (pre-rope)
__device__ float g_k[(size_t)MROWS*HD];     // k projection fp32 (pre-rope)
__device__ float g_attn[(size_t)MROWS*DM];  // attention output fp32
__device__ __nv_bfloat16 g_ahi[(size_t)MROWS*DM];   // split activations
__device__ __nv_bfloat16 g_alo[(size_t)MROWS*DM];
__device__ __nv_bfloat16 g_wqT_hi[(size_t)DM*DM], g_wqT_lo[(size_t)DM*DM];
__device__ __nv_bfloat16 g_woT_hi[(size_t)DM*DM], g_woT_lo[(size_t)DM*DM];
__device__ __nv_bfloat16 g_wkT_hi[(size_t)HD*DM], g_wkT_lo[(size_t)HD*DM];
__device__ __nv_bfloat16 g_wvT_hi[(size_t)HD*DM], g_wvT_lo[(size_t)HD*DM];
// attention operands (bf16 hi/lo)
__device__ __nv_bfloat16 g_qhi[(size_t)MROWS*DM],  g_qlo[(size_t)MROWS*DM];   // [B,S,NH,HD]
__device__ __nv_bfloat16 g_khi[(size_t)MROWS*HD],  g_klo[(size_t)MROWS*HD];   // [B,S,HD]
__device__ __nv_bfloat16 g_vthi[(size_t)MROWS*HD], g_vtlo[(size_t)MROWS*HD];  // [B,HD,S]

// ---------------------------------------------------------------------------
// helpers
// ---------------------------------------------------------------------------
__device__ __forceinline__ unsigned s2u(const void* p) {
    unsigned a;
    asm("{ .reg .u64 t; cvta.to.shared.u64 t, %1; cvt.u32.u64 %0, t; }"
        : "=r"(a) : "l"(p));
    return a;
}
__device__ __forceinline__ void ldmx4(unsigned r[4], unsigned addr) {
    asm volatile("ldmatrix.sync.aligned.m8n8.x4.shared.b16 {%0,%1,%2,%3}, [%4];"
                 : "=r"(r[0]), "=r"(r[1]), "=r"(r[2]), "=r"(r[3]) : "r"(addr));
}
__device__ __forceinline__ void mma_bf16(float c[4], const unsigned a[4],
                                         const unsigned b[2]) {
    asm volatile(
        "mma.sync.aligned.m16n8k16.row.col.f32.bf16.bf16.f32 "
        "{%0,%1,%2,%3}, {%4,%5,%6,%7}, {%8,%9}, {%0,%1,%2,%3};"
        : "+f"(c[0]), "+f"(c[1]), "+f"(c[2]), "+f"(c[3])
        : "r"(a[0]), "r"(a[1]), "r"(a[2]), "r"(a[3]), "r"(b[0]), "r"(b[1]));
}
__device__ __forceinline__ unsigned pack_bf16(float a, float b) {
    __nv_bfloat162 t = __floats2bfloat162_rn(a, b);
    return *(unsigned*)&t;
}
__device__ __forceinline__ void cpa16(unsigned dst, const void* src) {
    asm volatile("cp.async.cg.shared.global [%0], [%1], 16;"
                 :: "r"(dst), "l"(src) : "memory");
}
__device__ __forceinline__ void cp_commit() {
    asm volatile("cp.async.commit_group;" ::: "memory");
}
template<int N> __device__ __forceinline__ void cp_wait() {
    asm volatile("cp.async.wait_group %0;" :: "n"(N) : "memory");
}

// ---------------------------------------------------------------------------
// bf16x3 GEMM (mma.sync):  C[M,Ntot] = (Ahi+Alo)[M,K] @ (Bhi+Blo)[Ntot,K]^T + bias
// BM=BN=128, BK=64 (SW128 smem), 256 threads, cp.async 2-stage pipeline.
// ---------------------------------------------------------------------------
__global__ void __launch_bounds__(256) gemm_tc(
    const __nv_bfloat16* __restrict__ Ahi, const __nv_bfloat16* __restrict__ Alo,
    const __nv_bfloat16* __restrict__ Bhi, const __nv_bfloat16* __restrict__ Blo,
    const float* __restrict__ bias, float* __restrict__ C, int Ntot)
{
    extern __shared__ __align__(128) char smem[];
    const unsigned sb = s2u(smem);
    const int tid = threadIdx.x;
    const int m0 = blockIdx.y * 128;
    const int n0 = blockIdx.x * 128;

    const int lane = tid & 31, w = tid >> 5;
    const int wm = w & 3, wn = w >> 2;        // warp tile: 32 (M) x 64 (N)

    float acc[2][8][4];
    #pragma unroll
    for (int mt = 0; mt < 2; mt++)
        #pragma unroll
        for (int j = 0; j < 8; j++)
            #pragma unroll
            for (int e = 0; e < 4; e++) acc[mt][j][e] = 0.f;

    int arow[2];
    #pragma unroll
    for (int mt = 0; mt < 2; mt++)
        arow[mt] = wm*32 + mt*16 + (lane & 7) + ((lane >> 3) & 1) * 8;
    const int acolh = (lane >> 4) * 16;                                // bytes
    const int brow4 = wn*64 + (lane & 7) + ((lane >> 4) & 1) * 8;      // x4 B rows
    const int bcol8 = ((lane >> 3) & 1) * 16;                          // bytes

    auto load_chunk = [&](int c, int buf) {
        const int k0 = c * 64;
        const unsigned base = sb + buf * 65536u;
        #pragma unroll
        for (int t = 0; t < 4; t++) {
            int i = tid + t * 256;
            int rr = i >> 3, q = i & 7;
            size_t ga = (size_t)(m0 + rr) * KDIM + k0 + q * 8;
            size_t gb = (size_t)(n0 + rr) * KDIM + k0 + q * 8;
            int so = rr * 128 + q * 16;
            int sw = so ^ ((so >> 3) & 0x70);
            cpa16(base + sw,          Ahi + ga);
            cpa16(base + 16384 + sw,  Alo + ga);
            cpa16(base + 32768 + sw,  Bhi + gb);
            cpa16(base + 49152 + sw,  Blo + gb);
        }
    };

    load_chunk(0, 0);
    cp_commit();

    for (int c = 0; c < NCHUNK; c++) {
        if (c + 1 < NCHUNK) {
            load_chunk(c + 1, (c + 1) & 1);
            cp_commit();
            cp_wait<1>();
        } else {
            cp_wait<0>();
        }
        __syncthreads();

        const unsigned sbuf = sb + (unsigned)(c & 1) * 65536u;
        const unsigned sA_hi = sbuf, sA_lo = sbuf + 16384;
        const unsigned sB_hi = sbuf + 32768, sB_lo = sbuf + 49152;

        #pragma unroll
        for (int ks = 0; ks < 4; ks++) {
            unsigned Ah[2][4], Al[2][4], Bh[8][2], Bl[8][2];
            #pragma unroll
            for (int mt = 0; mt < 2; mt++) {
                int off = arow[mt] * 128 + ks * 32 + acolh;
                off ^= (off >> 3) & 0x70;
                ldmx4(Ah[mt], sA_hi + off);
                ldmx4(Al[mt], sA_lo + off);
            }
            #pragma unroll
            for (int jj = 0; jj < 4; jj++) {
                int off = (brow4 + jj * 16) * 128 + ks * 32 + bcol8;
                off ^= (off >> 3) & 0x70;
                unsigned th[4], tl[4];
                ldmx4(th, sB_hi + off);
                ldmx4(tl, sB_lo + off);
                Bh[2*jj][0] = th[0]; Bh[2*jj][1] = th[1];
                Bh[2*jj+1][0] = th[2]; Bh[2*jj+1][1] = th[3];
                Bl[2*jj][0] = tl[0]; Bl[2*jj][1] = tl[1];
                Bl[2*jj+1][0] = tl[2]; Bl[2*jj+1][1] = tl[3];
            }
            #pragma unroll
            for (int mt = 0; mt < 2; mt++)
                #pragma unroll
                for (int j = 0; j < 8; j++) {
                    mma_bf16(acc[mt][j], Ah[mt], Bh[j]);
                    mma_bf16(acc[mt][j], Ah[mt], Bl[j]);
                    mma_bf16(acc[mt][j], Al[mt], Bh[j]);
                }
        }
        __syncthreads();
    }

    #pragma unroll
    for (int mt = 0; mt < 2; mt++) {
        int r0 = m0 + wm*32 + mt*16 + (lane >> 2);
        #pragma unroll
        for (int j = 0; j < 8; j++) {
            int col = n0 + wn*64 + j*8 + (lane & 3) * 2;
            float2 o0, o1;
            o0.x = acc[mt][j][0] + bias[col];
            o0.y = acc[mt][j][1] + bias[col + 1];
            o1.x = acc[mt][j][2] + bias[col];
            o1.y = acc[mt][j][3] + bias[col + 1];
            *(float2*)(C + (size_t)r0 * Ntot + col)       = o0;
            *(float2*)(C + (size_t)(r0 + 8) * Ntot + col) = o1;
        }
    }
}

// ---------------------------------------------------------------------------
// fp32 -> bf16 hi/lo split (elementwise)
// ---------------------------------------------------------------------------
__global__ void convert_split(const float* __restrict__ a,
                              __nv_bfloat16* __restrict__ hi,
                              __nv_bfloat16* __restrict__ lo)
{
    size_t i = ((size_t)blockIdx.x * blockDim.x + threadIdx.x) * 4;
    float4 v = *(const float4*)(a + i);
    __nv_bfloat16 h0 = __float2bfloat16(v.x);
    __nv_bfloat16 h1 = __float2bfloat16(v.y);
    __nv_bfloat16 h2 = __float2bfloat16(v.z);
    __nv_bfloat16 h3 = __float2bfloat16(v.w);
    __nv_bfloat16 l0 = __float2bfloat16(v.x - __bfloat162float(h0));
    __nv_bfloat16 l1 = __float2bfloat16(v.y - __bfloat162float(h1));
    __nv_bfloat16 l2 = __float2bfloat16(v.z - __bfloat162float(h2));
    __nv_bfloat16 l3 = __float2bfloat16(v.w - __bfloat162float(h3));
    __nv_bfloat162 ph0; ph0.x = h0; ph0.y = h1;
    __nv_bfloat162 ph1; ph1.x = h2; ph1.y = h3;
    __nv_bfloat162 pl0; pl0.x = l0; pl0.y = l1;
    __nv_bfloat162 pl1; pl1.x = l2; pl1.y = l3;
    *(__nv_bfloat162*)(hi + i)     = ph0;
    *(__nv_bfloat162*)(hi + i + 2) = ph1;
    *(__nv_bfloat162*)(lo + i)     = pl0;
    *(__nv_bfloat162*)(lo + i + 2) = pl1;
}

// ---------------------------------------------------------------------------
// weight transpose + split:  w[K,N] fp32  ->  hi/lo[N,K] bf16
// ---------------------------------------------------------------------------
__global__ void transpose_split(const float* __restrict__ w,
                                __nv_bfloat16* __restrict__ hi,
                                __nv_bfloat16* __restrict__ lo,
                                int K, int N)
{
    __shared__ float tile[32][33];
    const int k0 = blockIdx.x * 32, n0 = blockIdx.y * 32;
    const int tx = threadIdx.x, ty = threadIdx.y;   // 32 x 8
    #pragma unroll
    for (int i = 0; i < 32; i += 8)
        tile[ty + i][tx] = w[(size_t)(k0 + ty + i) * N + n0 + tx];
    __syncthreads();
    #pragma unroll
    for (int i = 0; i < 32; i += 8) {
        float v = tile[tx][ty + i];
        __nv_bfloat16 h = __float2bfloat16(v);
        size_t o = (size_t)(n0 + ty + i) * K + k0 + tx;
        hi[o] = h;
        lo[o] = __float2bfloat16(v - __bfloat162float(h));
    }
}

// ---------------------------------------------------------------------------
// V transpose + split:  vh[B,S,HD] fp32 -> vthi/vtlo[B,HD,S] bf16
// ---------------------------------------------------------------------------
__global__ void vt_split(const float* __restrict__ v,
                         __nv_bfloat16* __restrict__ hi,
                         __nv_bfloat16* __restrict__ lo)
{
    __shared__ float tile[32][33];
    const int s0 = blockIdx.x * 32, h0 = blockIdx.y * 32, b = blockIdx.z;
    const int tx = threadIdx.x, ty = threadIdx.y;   // 32 x 8
    #pragma unroll
    for (int i = 0; i < 32; i += 8)
        tile[ty + i][tx] = v[((size_t)b*SEQ + s0 + ty + i) * HD + h0 + tx];
    __syncthreads();
    #pragma unroll
    for (int i = 0; i < 32; i += 8) {
        float val = tile[tx][ty + i];   // row s0+tx, col h0+ty+i
        __nv_bfloat16 h = __float2bfloat16(val);
        size_t o = ((size_t)b*HD + h0 + ty + i) * SEQ + s0 + tx;
        hi[o] = h;
        lo[o] = __float2bfloat16(val - __bfloat162float(h));
    }
}

// ---------------------------------------------------------------------------
// RoPE (fp32 in, bf16 hi/lo out)
// ---------------------------------------------------------------------------
__global__ void rope_q_split(const float* __restrict__ q,
                             __nv_bfloat16* __restrict__ qhi,
                             __nv_bfloat16* __restrict__ qlo)
{
    int idx = blockIdx.x * blockDim.x + threadIdx.x;   // over B*S*H*64 pairs
    int i = idx & 63;
    int s = (idx >> 10) & 2047;
    float inv = 1.0f / powf(10000.0f, (float)(2*i) * (1.0f/128.0f));
    float ang = (float)s * inv;
    float sn, cs;
    sincosf(ang, &sn, &cs);
    float2 v = *(const float2*)(q + 2*(size_t)idx);
    float o1 = v.x*cs - v.y*sn;
    float o2 = v.x*sn + v.y*cs;
    __nv_bfloat162 h = __floats2bfloat162_rn(o1, o2);
    __nv_bfloat162 l = __floats2bfloat162_rn(o1 - __bfloat162float(h.x),
                                             o2 - __bfloat162float(h.y));
    *(__nv_bfloat162*)(qhi + 2*(size_t)idx) = h;
    *(__nv_bfloat162*)(qlo + 2*(size_t)idx) = l;
}

__global__ void rope_k_split(const float* __restrict__ k, float* __restrict__ kh,
                             __nv_bfloat16* __restrict__ khi,
                             __nv_bfloat16* __restrict__ klo)
{
    int idx = blockIdx.x * blockDim.x + threadIdx.x;   // over B*S*64 pairs
    int i = idx & 63;
    int s = (idx >> 6) & 2047;
    float inv = 1.0f / powf(10000.0f, (float)(2*i) * (1.0f/128.0f));
    float ang = (float)s * inv;
    float sn, cs;
    sincosf(ang, &sn, &cs);
    float2 v = *(const float2*)(k + 2*(size_t)idx);
    float o1 = v.x*cs - v.y*sn;
    float o2 = v.x*sn + v.y*cs;
    float2 of; of.x = o1; of.y = o2;
    *(float2*)(kh + 2*(size_t)idx) = of;
    __nv_bfloat162 h = __floats2bfloat162_rn(o1, o2);
    __nv_bfloat162 l = __floats2bfloat162_rn(o1 - __bfloat162float(h.x),
                                             o2 - __bfloat162float(h.y));
    *(__nv_bfloat162*)(khi + 2*(size_t)idx) = h;
    *(__nv_bfloat162*)(klo + 2*(size_t)idx) = l;
}

// ---------------------------------------------------------------------------
// Tensor-core causal MQA flash attention (bf16x3, fp32 softmax).
// CTA: 128 q-rows x 64-kv tiles, 8 warps, warp = 16 q-rows.
// cp.async double-buffered K/V, heavy CTAs launch first, ldmx4 fragments.
// ---------------------------------------------------------------------------
#define ATT_SCALE 0.08838834764831845f
#define PQ  136   // smem pitch for Q/K tiles (bf16 elems)
#define PVT 72    // smem pitch for Vt tiles (bf16 elems)
#define KVBUF (128*PQ + 2*128*PVT)   // elems per K/V stage: KH,KL + VH,VL

__global__ void __launch_bounds__(256) flash_tc(
    const __nv_bfloat16* __restrict__ Qhi, const __nv_bfloat16* __restrict__ Qlo,
    const __nv_bfloat16* __restrict__ Khi, const __nv_bfloat16* __restrict__ Klo,
    const __nv_bfloat16* __restrict__ Vthi, const __nv_bfloat16* __restrict__ Vtlo,
    float* __restrict__ O)
{
    extern __shared__ __align__(128) __nv_bfloat16 sm[];
    __nv_bfloat16* QH = sm;                    // 128 x PQ
    __nv_bfloat16* QL = QH + 128*PQ;

    const int tid = threadIdx.x;
    const int lane = tid & 31, w = tid >> 5;
    const int b = blockIdx.z, h = blockIdx.y;
    const int qb = (int)gridDim.x - 1 - (int)blockIdx.x;   // heavy CTAs first
    const int row0 = qb * 128;

    // stage Q (hi/lo)
    #pragma unroll
    for (int t = 0; t < 8; t++) {
        int u = tid + t*256;
        int r = u >> 4, c = (u & 15) * 8;
        size_t g = (((size_t)b*SEQ + row0 + r)*NH + h)*HD + c;
        *(uint4*)&QH[r*PQ + c] = *(const uint4*)&Qhi[g];
        *(uint4*)&QL[r*PQ + c] = *(const uint4*)&Qlo[g];
    }

    auto load_kv = [&](int t, int buf) {
        __nv_bfloat16* base = sm + 2*128*PQ + buf*KVBUF;
        __nv_bfloat16* KHp = base;
        __nv_bfloat16* KLp = base + 64*PQ;
        __nv_bfloat16* VHp = base + 128*PQ;
        __nv_bfloat16* VLp = VHp + 128*PVT;
        const int kb = t * 64;
        #pragma unroll
        for (int tt = 0; tt < 4; tt++) {
            int u = tid + tt*256;
            {
                int r = u >> 4, c = (u & 15) * 8;
                size_t g = ((size_t)b*SEQ + kb + r)*HD + c;
                cpa16(s2u(&KHp[r*PQ + c]), Khi + g);
                cpa16(s2u(&KLp[r*PQ + c]), Klo + g);
            }
            {
                int r = u >> 3, c = (u & 7) * 8;
                size_t g = ((size_t)b*HD + r)*SEQ + kb + c;
                cpa16(s2u(&VHp[r*PVT + c]), Vthi + g);
                cpa16(s2u(&VLp[r*PVT + c]), Vtlo + g);
            }
        }
    };

    load_kv(0, 0);
    cp_commit();
    __syncthreads();   // Q staged

    // Q fragments in registers (warp rows [w*16, w*16+16))
    unsigned qh[8][4], ql[8][4];
    {
        const int ar = w*16 + (lane & 7) + ((lane >> 3) & 1) * 8;
        const int ac = (lane >> 4) * 8;
        #pragma unroll
        for (int kt = 0; kt < 8; kt++) {
            ldmx4(qh[kt], s2u(&QH[ar*PQ + kt*16 + ac]));
            ldmx4(ql[kt], s2u(&QL[ar*PQ + kt*16 + ac]));
        }
    }

    float m0 = -INFINITY, m1 = -INFINITY, l0 = 0.f, l1 = 0.f;
    float o[16][4];
    #pragma unroll
    for (int n = 0; n < 16; n++)
        #pragma unroll
        for (int e = 0; e < 4; e++) o[n][e] = 0.f;

    const int qr0 = row0 + w*16 + (lane >> 2);
    const int qr1 = qr0 + 8;
    const int kcol = 2*(lane & 3);
    const int krow4 = (lane & 7) + ((lane >> 4) & 1) * 8;
    const int kchalf = ((lane >> 3) & 1) * 8;

    const int n_tiles = 2*qb + 2;
    for (int t = 0; t < n_tiles; t++) {
        const int kb = t*64;
        if (t + 1 < n_tiles) {
            load_kv(t + 1, (t + 1) & 1);
            cp_commit();
            cp_wait<1>();
        } else {
            cp_wait<0>();
        }
        __syncthreads();

        __nv_bfloat16* base = sm + 2*128*PQ + (t & 1)*KVBUF;
        __nv_bfloat16* KH = base;
        __nv_bfloat16* KL = base + 64*PQ;
        __nv_bfloat16* VH = base + 128*PQ;
        __nv_bfloat16* VL = VH + 128*PVT;

        // S = Q K^T  (bf16x3, ldmx4 K fragments)
        float s[8][4];
        #pragma unroll
        for (int j = 0; j < 8; j++)
            #pragma unroll
            for (int e = 0; e < 4; e++) s[j][e] = 0.f;

        #pragma unroll
        for (int kt = 0; kt < 8; kt++) {
            #pragma unroll
            for (int jj = 0; jj < 4; jj++) {
                unsigned th[4], tl[4];
                int off = (jj*16 + krow4)*PQ + kt*16 + kchalf;
                ldmx4(th, s2u(&KH[off]));
                ldmx4(tl, s2u(&KL[off]));
                mma_bf16(s[2*jj],   qh[kt], &th[0]);
                mma_bf16(s[2*jj],   qh[kt], &tl[0]);
                mma_bf16(s[2*jj],   ql[kt], &th[0]);
                mma_bf16(s[2*jj+1], qh[kt], &th[2]);
                mma_bf16(s[2*jj+1], qh[kt], &tl[2]);
                mma_bf16(s[2*jj+1], ql[kt], &th[2]);
            }
        }

        // causal mask + scale + row max
        float tm0 = -INFINITY, tm1 = -INFINITY;
        #pragma unroll
        for (int j = 0; j < 8; j++) {
            int c0 = kb + j*8 + kcol;
            s[j][0] = (c0     <= qr0) ? s[j][0]*ATT_SCALE : -INFINITY;
            s[j][1] = (c0 + 1 <= qr0) ? s[j][1]*ATT_SCALE : -INFINITY;
            s[j][2] = (c0     <= qr1) ? s[j][2]*ATT_SCALE : -INFINITY;
            s[j][3] = (c0 + 1 <= qr1) ? s[j][3]*ATT_SCALE : -INFINITY;
            tm0 = fmaxf(tm0, fmaxf(s[j][0], s[j][1]));
            tm1 = fmaxf(tm1, fmaxf(s[j][2], s[j][3]));
        }
        tm0 = fmaxf(tm0, __shfl_xor_sync(0xffffffffu, tm0, 1));
        tm0 = fmaxf(tm0, __shfl_xor_sync(0xffffffffu, tm0, 2));
        tm1 = fmaxf(tm1, __shfl_xor_sync(0xffffffffu, tm1, 1));
        tm1 = fmaxf(tm1, __shfl_xor_sync(0xffffffffu, tm1, 2));

        float mn0 = fmaxf(m0, tm0), mn1 = fmaxf(m1, tm1);
        float rs0 = 0.f, rs1 = 0.f;
        unsigned pH[8][2], pL[8][2];
        #pragma unroll
        for (int j = 0; j < 8; j++) {
            float p0 = __expf(s[j][0] - mn0), p1 = __expf(s[j][1] - mn0);
            float p2 = __expf(s[j][2] - mn1), p3 = __expf(s[j][3] - mn1);
            rs0 += p0 + p1; rs1 += p2 + p3;
            __nv_bfloat162 h01 = __floats2bfloat162_rn(p0, p1);
            __nv_bfloat162 h23 = __floats2bfloat162_rn(p2, p3);
            pH[j][0] = *(unsigned*)&h01;
            pH[j][1] = *(unsigned*)&h23;
            pL[j][0] = pack_bf16(p0 - __bfloat162float(h01.x),
                                 p1 - __bfloat162float(h01.y));
            pL[j][1] = pack_bf16(p2 - __bfloat162float(h23.x),
                                 p3 - __bfloat162float(h23.y));
        }
        rs0 += __shfl_xor_sync(0xffffffffu, rs0, 1);
        rs0 += __shfl_xor_sync(0xffffffffu, rs0, 2);
        rs1 += __shfl_xor_sync(0xffffffffu, rs1, 1);
        rs1 += __shfl_xor_sync(0xffffffffu, rs1, 2);

        float al0 = __expf(m0 - mn0), al1 = __expf(m1 - mn1);
        m0 = mn0; m1 = mn1;
        l0 = l0*al0 + rs0; l1 = l1*al1 + rs1;
        #pragma unroll
        for (int n = 0; n < 16; n++) {
            o[n][0] *= al0; o[n][1] *= al0;
            o[n][2] *= al1; o[n][3] *= al1;
        }

        // O += P V  (bf16x3; ldmx4 V fragments)
        #pragma unroll
        for (int ks = 0; ks < 4; ks++) {
            unsigned aH[4] = {pH[2*ks][0], pH[2*ks][1], pH[2*ks+1][0], pH[2*ks+1][1]};
            unsigned aL[4] = {pL[2*ks][0], pL[2*ks][1], pL[2*ks+1][0], pL[2*ks+1][1]};
            #pragma unroll
            for (int nn = 0; nn < 8; nn++) {
                unsigned vh4[4], vl4[4];
                int off = (nn*16 + krow4)*PVT + ks*16 + kchalf;
                ldmx4(vh4, s2u(&VH[off]));
                ldmx4(vl4, s2u(&VL[off]));
                mma_bf16(o[2*nn],   aH, &vh4[0]);
                mma_bf16(o[2*nn],   aH, &vl4[0]);
                mma_bf16(o[2*nn],   aL, &vh4[0]);
                mma_bf16(o[2*nn+1], aH, &vh4[2]);
                mma_bf16(o[2*nn+1], aH, &vl4[2]);
                mma_bf16(o[2*nn+1], aL, &vh4[2]);
            }
        }
        __syncthreads();
    }

    // epilogue
    const float i0 = 1.f / l0, i1 = 1.f / l1;
    #pragma unroll
    for (int n = 0; n < 16; n++) {
        int col = n*8 + kcol;
        size_t g0 = (((size_t)b*SEQ + qr0)*NH + h)*HD + col;
        size_t g1 = (((size_t)b*SEQ + qr1)*NH + h)*HD + col;
        float2 w0; w0.x = o[n][0]*i0; w0.y = o[n][1]*i0;
        float2 w1; w1.x = o[n][2]*i1; w1.y = o[n][3]*i1;
        *(float2*)&O[g0] = w0;
        *(float2*)&O[g1] = w1;
    }
}

// ---------------------------------------------------------------------------
extern "C" void kernel_launch(void* const* d_in, const int* in_sizes, int n_in,
                              void* d_out, int out_size)
{
    const float* x  = (const float*)d_in[0];
    const float* wq = (const float*)d_in[1];
    const float* bq = (const float*)d_in[2];
    const float* wk = (const float*)d_in[3];
    const float* bk = (const float*)d_in[4];
    const float* wv = (const float*)d_in[5];
    const float* bv = (const float*)d_in[6];
    const float* wo = (const float*)d_in[7];
    const float* bo = (const float*)d_in[8];

    float* out = (float*)d_out;                      // (B,S,D)
    float* kh  = out + (size_t)MROWS*DM;             // (B,1,S,HD)
    float* vh  = kh  + (size_t)MROWS*HD;             // (B,1,S,HD)

    float *qp, *kp, *ap;
    cudaGetSymbolAddress((void**)&qp, g_q);
    cudaGetSymbolAddress((void**)&kp, g_k);
    cudaGetSymbolAddress((void**)&ap, g_attn);
    __nv_bfloat16 *ahi, *alo, *wqh, *wql, *wkh, *wkl, *wvh, *wvl, *woh, *wol;
    __nv_bfloat16 *qhi, *qlo, *khi, *klo, *vthi, *vtlo;
    cudaGetSymbolAddress((void**)&ahi, g_ahi);
    cudaGetSymbolAddress((void**)&alo, g_alo);
    cudaGetSymbolAddress((void**)&wqh, g_wqT_hi);
    cudaGetSymbolAddress((void**)&wql, g_wqT_lo);
    cudaGetSymbolAddress((void**)&wkh, g_wkT_hi);
    cudaGetSymbolAddress((void**)&wkl, g_wkT_lo);
    cudaGetSymbolAddress((void**)&wvh, g_wvT_hi);
    cudaGetSymbolAddress((void**)&wvl, g_wvT_lo);
    cudaGetSymbolAddress((void**)&woh, g_woT_hi);
    cudaGetSymbolAddress((void**)&wol, g_woT_lo);
    cudaGetSymbolAddress((void**)&qhi, g_qhi);
    cudaGetSymbolAddress((void**)&qlo, g_qlo);
    cudaGetSymbolAddress((void**)&khi, g_khi);
    cudaGetSymbolAddress((void**)&klo, g_klo);
    cudaGetSymbolAddress((void**)&vthi, g_vthi);
    cudaGetSymbolAddress((void**)&vtlo, g_vtlo);

    const int GEMM_SMEM  = 2 * 65536;                        // 131,072 B
    const int FLASH_SMEM = (2*128*PQ + 2*KVBUF) * 2;         // 212,992 B
    cudaFuncSetAttribute(gemm_tc, cudaFuncAttributeMaxDynamicSharedMemorySize,
                         GEMM_SMEM);
    cudaFuncSetAttribute(flash_tc, cudaFuncAttributeMaxDynamicSharedMemorySize,
                         FLASH_SMEM);

    // split activations and weights to bf16 hi/lo
    convert_split<<<(size_t)MROWS*DM/1024, 256>>>(x, ahi, alo);
    transpose_split<<<dim3(DM/32, DM/32), dim3(32,8)>>>(wq, wqh, wql, DM, DM);
    transpose_split<<<dim3(DM/32, HD/32), dim3(32,8)>>>(wk, wkh, wkl, DM, HD);
    transpose_split<<<dim3(DM/32, HD/32), dim3(32,8)>>>(wv, wvh, wvl, DM, HD);
    transpose_split<<<dim3(DM/32, DM/32), dim3(32,8)>>>(wo, woh, wol, DM, DM);

    // projections (tensor cores, bf16x3, cp.async pipelined)
    gemm_tc<<<dim3(DM/128, MROWS/128), 256, GEMM_SMEM>>>(ahi, alo, wqh, wql, bq, qp, DM);
    gemm_tc<<<dim3(1,      MROWS/128), 256, GEMM_SMEM>>>(ahi, alo, wkh, wkl, bk, kp, HD);
    gemm_tc<<<dim3(1,      MROWS/128), 256, GEMM_SMEM>>>(ahi, alo, wvh, wvl, bv, vh, HD);

    // rope + attention operand prep
    rope_q_split<<<(MROWS*NH*64)/256, 256>>>(qp, qhi, qlo);
    rope_k_split<<<(MROWS*64)/256, 256>>>(kp, kh, khi, klo);
    vt_split<<<dim3(SEQ/32, HD/32, BATCH), dim3(32,8)>>>(vh, vthi, vtlo);

    // attention (tensor cores, bf16x3)
    flash_tc<<<dim3(16, 16, 4), 256, FLASH_SMEM>>>(qhi, qlo, khi, klo, vthi, vtlo, ap);

    // output projection
    convert_split<<<(size_t)MROWS*DM/1024, 256>>>(ap, ahi, alo);
    gemm_tc<<<dim3(DM/128, MROWS/128), 256, GEMM_SMEM>>>(ahi, alo, woh, wol, bo, out, DM);
}

// round 6
// speedup vs baseline: 3.1036x; 1.0566x over previous
#include <cuda_runtime.h>
#include <cuda_bf16.h>
#include <math.h>

#define BATCH 4
#define SEQ   2048
#define NH    16
#define HD    128
#define DM    2048
#define MROWS (BATCH*SEQ)
#define KDIM  2048
#define NCHUNK (KDIM/64)

// ---------------------------------------------------------------------------
// scratch (device globals; no cudaMalloc anywhere)
// ---------------------------------------------------------------------------
__device__ __nv_bfloat16 g_ahi[(size_t)MROWS*DM];   // split activations (x, then attn out)
__device__ __nv_bfloat16 g_alo[(size_t)MROWS*DM];
__device__ __nv_bfloat16 g_wqT_hi[(size_t)DM*DM], g_wqT_lo[(size_t)DM*DM];
__device__ __nv_bfloat16 g_woT_hi[(size_t)DM*DM], g_woT_lo[(size_t)DM*DM];
__device__ __nv_bfloat16 g_wkT_hi[(size_t)HD*DM], g_wkT_lo[(size_t)HD*DM];
__device__ __nv_bfloat16 g_wvT_hi[(size_t)HD*DM], g_wvT_lo[(size_t)HD*DM];
// attention operands (bf16 hi/lo)
__device__ __nv_bfloat16 g_qhi[(size_t)MROWS*DM],  g_qlo[(size_t)MROWS*DM];   // [B,S,NH,HD]
__device__ __nv_bfloat16 g_khi[(size_t)MROWS*HD],  g_klo[(size_t)MROWS*HD];   // [B,S,HD]
__device__ __nv_bfloat16 g_vthi[(size_t)MROWS*HD], g_vtlo[(size_t)MROWS*HD];  // [B,HD,S]

// ---------------------------------------------------------------------------
// helpers
// ---------------------------------------------------------------------------
__device__ __forceinline__ unsigned s2u(const void* p) {
    unsigned a;
    asm("{ .reg .u64 t; cvta.to.shared.u64 t, %1; cvt.u32.u64 %0, t; }"
        : "=r"(a) : "l"(p));
    return a;
}
__device__ __forceinline__ void ldmx4(unsigned r[4], unsigned addr) {
    asm volatile("ldmatrix.sync.aligned.m8n8.x4.shared.b16 {%0,%1,%2,%3}, [%4];"
                 : "=r"(r[0]), "=r"(r[1]), "=r"(r[2]), "=r"(r[3]) : "r"(addr));
}
__device__ __forceinline__ void mma_bf16(float c[4], const unsigned a[4],
                                         const unsigned b[2]) {
    asm volatile(
        "mma.sync.aligned.m16n8k16.row.col.f32.bf16.bf16.f32 "
        "{%0,%1,%2,%3}, {%4,%5,%6,%7}, {%8,%9}, {%0,%1,%2,%3};"
        : "+f"(c[0]), "+f"(c[1]), "+f"(c[2]), "+f"(c[3])
        : "r"(a[0]), "r"(a[1]), "r"(a[2]), "r"(a[3]), "r"(b[0]), "r"(b[1]));
}
__device__ __forceinline__ unsigned pack_bf16(float a, float b) {
    __nv_bfloat162 t = __floats2bfloat162_rn(a, b);
    return *(unsigned*)&t;
}
__device__ __forceinline__ void cpa16(unsigned dst, const void* src) {
    asm volatile("cp.async.cg.shared.global [%0], [%1], 16;"
                 :: "r"(dst), "l"(src) : "memory");
}
__device__ __forceinline__ void cp_commit() {
    asm volatile("cp.async.commit_group;" ::: "memory");
}
template<int N> __device__ __forceinline__ void cp_wait() {
    asm volatile("cp.async.wait_group %0;" :: "n"(N) : "memory");
}

// ---------------------------------------------------------------------------
// shared bf16x3 GEMM mainloop: acc[2][8][4] = (Ahi+Alo)[128,K] @ (Bhi+Blo)[128,K]^T
// 3-stage cp.async ring, one __syncthreads per chunk.
// ---------------------------------------------------------------------------
__device__ __forceinline__ void gemm_mainloop(
    const __nv_bfloat16* __restrict__ Ahi, const __nv_bfloat16* __restrict__ Alo,
    const __nv_bfloat16* __restrict__ Bhi, const __nv_bfloat16* __restrict__ Blo,
    int m0, int n0, char* smem, float acc[2][8][4])
{
    const unsigned sb = s2u(smem);
    const int tid = threadIdx.x;
    const int lane = tid & 31, w = tid >> 5;
    const int wm = w & 3, wn = w >> 2;

    #pragma unroll
    for (int mt = 0; mt < 2; mt++)
        #pragma unroll
        for (int j = 0; j < 8; j++)
            #pragma unroll
            for (int e = 0; e < 4; e++) acc[mt][j][e] = 0.f;

    int arow[2];
    #pragma unroll
    for (int mt = 0; mt < 2; mt++)
        arow[mt] = wm*32 + mt*16 + (lane & 7) + ((lane >> 3) & 1) * 8;
    const int acolh = (lane >> 4) * 16;                                // bytes
    const int brow4 = wn*64 + (lane & 7) + ((lane >> 4) & 1) * 8;
    const int bcol8 = ((lane >> 3) & 1) * 16;                          // bytes

    auto load_chunk = [&](int c, int st) {
        const int k0 = c * 64;
        const unsigned base = sb + (unsigned)st * 65536u;
        #pragma unroll
        for (int t = 0; t < 4; t++) {
            int i = tid + t * 256;
            int rr = i >> 3, q = i & 7;
            size_t ga = (size_t)(m0 + rr) * KDIM + k0 + q * 8;
            size_t gb = (size_t)(n0 + rr) * KDIM + k0 + q * 8;
            int so = rr * 128 + q * 16;
            int sw = so ^ ((so >> 3) & 0x70);
            cpa16(base + sw,          Ahi + ga);
            cpa16(base + 16384 + sw,  Alo + ga);
            cpa16(base + 32768 + sw,  Bhi + gb);
            cpa16(base + 49152 + sw,  Blo + gb);
        }
    };

    load_chunk(0, 0); cp_commit();
    load_chunk(1, 1); cp_commit();

    for (int c = 0; c < NCHUNK; c++) {
        if (c + 2 < NCHUNK) cp_wait<1>(); else cp_wait<0>();
        __syncthreads();
        if (c + 2 < NCHUNK) { load_chunk(c + 2, (c + 2) % 3); cp_commit(); }

        const unsigned sbuf = sb + (unsigned)(c % 3) * 65536u;
        const unsigned sA_hi = sbuf, sA_lo = sbuf + 16384;
        const unsigned sB_hi = sbuf + 32768, sB_lo = sbuf + 49152;

        #pragma unroll
        for (int ks = 0; ks < 4; ks++) {
            unsigned Ah[2][4], Al[2][4], Bh[8][2], Bl[8][2];
            #pragma unroll
            for (int mt = 0; mt < 2; mt++) {
                int off = arow[mt] * 128 + ks * 32 + acolh;
                off ^= (off >> 3) & 0x70;
                ldmx4(Ah[mt], sA_hi + off);
                ldmx4(Al[mt], sA_lo + off);
            }
            #pragma unroll
            for (int jj = 0; jj < 4; jj++) {
                int off = (brow4 + jj * 16) * 128 + ks * 32 + bcol8;
                off ^= (off >> 3) & 0x70;
                unsigned th[4], tl[4];
                ldmx4(th, sB_hi + off);
                ldmx4(tl, sB_lo + off);
                Bh[2*jj][0] = th[0]; Bh[2*jj][1] = th[1];
                Bh[2*jj+1][0] = th[2]; Bh[2*jj+1][1] = th[3];
                Bl[2*jj][0] = tl[0]; Bl[2*jj][1] = tl[1];
                Bl[2*jj+1][0] = tl[2]; Bl[2*jj+1][1] = tl[3];
            }
            #pragma unroll
            for (int mt = 0; mt < 2; mt++)
                #pragma unroll
                for (int j = 0; j < 8; j++) {
                    mma_bf16(acc[mt][j], Ah[mt], Bh[j]);
                    mma_bf16(acc[mt][j], Ah[mt], Bl[j]);
                    mma_bf16(acc[mt][j], Al[mt], Bh[j]);
                }
        }
    }
}

// ---------------------------------------------------------------------------
// O-projection GEMM: plain bias + fp32 store
// ---------------------------------------------------------------------------
__global__ void __launch_bounds__(256) gemm_out(
    const __nv_bfloat16* __restrict__ Ahi, const __nv_bfloat16* __restrict__ Alo,
    const __nv_bfloat16* __restrict__ Bhi, const __nv_bfloat16* __restrict__ Blo,
    const float* __restrict__ bias, float* __restrict__ C)
{
    extern __shared__ __align__(128) char smem[];
    const int m0 = blockIdx.y * 128, n0 = blockIdx.x * 128;
    float acc[2][8][4];
    gemm_mainloop(Ahi, Alo, Bhi, Blo, m0, n0, smem, acc);

    const int lane = threadIdx.x & 31, w = threadIdx.x >> 5;
    const int wm = w & 3, wn = w >> 2;
    #pragma unroll
    for (int mt = 0; mt < 2; mt++) {
        int r0 = m0 + wm*32 + mt*16 + (lane >> 2);
        #pragma unroll
        for (int j = 0; j < 8; j++) {
            int col = n0 + wn*64 + j*8 + (lane & 3) * 2;
            float2 o0, o1;
            o0.x = acc[mt][j][0] + bias[col];
            o0.y = acc[mt][j][1] + bias[col + 1];
            o1.x = acc[mt][j][2] + bias[col];
            o1.y = acc[mt][j][3] + bias[col + 1];
            *(float2*)(C + (size_t)r0 * DM + col)       = o0;
            *(float2*)(C + (size_t)(r0 + 8) * DM + col) = o1;
        }
    }
}

// ---------------------------------------------------------------------------
// Q-projection GEMM: bias + RoPE + bf16 hi/lo split, fused in epilogue
// ---------------------------------------------------------------------------
__global__ void __launch_bounds__(256) gemm_q(
    const __nv_bfloat16* __restrict__ Ahi, const __nv_bfloat16* __restrict__ Alo,
    const __nv_bfloat16* __restrict__ Bhi, const __nv_bfloat16* __restrict__ Blo,
    const float* __restrict__ bias,
    __nv_bfloat16* __restrict__ qhi, __nv_bfloat16* __restrict__ qlo)
{
    extern __shared__ __align__(128) char smem[];
    const int m0 = blockIdx.y * 128, n0 = blockIdx.x * 128;
    float acc[2][8][4];
    gemm_mainloop(Ahi, Alo, Bhi, Blo, m0, n0, smem, acc);

    const int lane = threadIdx.x & 31, w = threadIdx.x >> 5;
    const int wm = w & 3, wn = w >> 2;
    #pragma unroll
    for (int j = 0; j < 8; j++) {
        int col = n0 + wn*64 + j*8 + (lane & 3) * 2;    // even
        float bx = bias[col], by = bias[col + 1];
        float inv = 1.0f / powf(10000.0f, (float)(col & 127) * (1.0f/128.0f));
        #pragma unroll
        for (int mt = 0; mt < 2; mt++) {
            int r0 = m0 + wm*32 + mt*16 + (lane >> 2);
            #pragma unroll
            for (int half = 0; half < 2; half++) {
                int r = r0 + half * 8;
                float x1 = acc[mt][j][2*half + 0] + bx;
                float x2 = acc[mt][j][2*half + 1] + by;
                float sn, cs;
                sincosf((float)(r & (SEQ-1)) * inv, &sn, &cs);
                float o1 = x1*cs - x2*sn;
                float o2 = x1*sn + x2*cs;
                __nv_bfloat162 hh = __floats2bfloat162_rn(o1, o2);
                __nv_bfloat162 ll = __floats2bfloat162_rn(
                    o1 - __bfloat162float(hh.x), o2 - __bfloat162float(hh.y));
                size_t g = (size_t)r * DM + col;
                *(__nv_bfloat162*)(qhi + g) = hh;
                *(__nv_bfloat162*)(qlo + g) = ll;
            }
        }
    }
}

// ---------------------------------------------------------------------------
// K+V projection in ONE launch: grid (2, 64); x==0 -> K (rope + kh + khi/klo),
// x==1 -> V (vh + transposed vthi/vtlo).
// ---------------------------------------------------------------------------
__global__ void __launch_bounds__(256) gemm_kv(
    const __nv_bfloat16* __restrict__ Ahi, const __nv_bfloat16* __restrict__ Alo,
    const __nv_bfloat16* __restrict__ wkh, const __nv_bfloat16* __restrict__ wkl,
    const __nv_bfloat16* __restrict__ wvh, const __nv_bfloat16* __restrict__ wvl,
    const float* __restrict__ bk, const float* __restrict__ bv,
    float* __restrict__ khout,
    __nv_bfloat16* __restrict__ khi, __nv_bfloat16* __restrict__ klo,
    float* __restrict__ vhout,
    __nv_bfloat16* __restrict__ vthi, __nv_bfloat16* __restrict__ vtlo)
{
    extern __shared__ __align__(128) char smem[];
    const int m0 = blockIdx.y * 128;
    const bool isK = (blockIdx.x == 0);
    const __nv_bfloat16* Bh = isK ? wkh : wvh;
    const __nv_bfloat16* Bl = isK ? wkl : wvl;
    const float* bias = isK ? bk : bv;

    float acc[2][8][4];
    gemm_mainloop(Ahi, Alo, Bh, Bl, m0, 0, smem, acc);

    const int lane = threadIdx.x & 31, w = threadIdx.x >> 5;
    const int wm = w & 3, wn = w >> 2;
    #pragma unroll
    for (int j = 0; j < 8; j++) {
        int col = wn*64 + j*8 + (lane & 3) * 2;    // 0..126 even
        float bx = bias[col], by = bias[col + 1];
        float inv = 1.0f / powf(10000.0f, (float)col * (1.0f/128.0f));
        #pragma unroll
        for (int mt = 0; mt < 2; mt++) {
            int r0 = m0 + wm*32 + mt*16 + (lane >> 2);
            #pragma unroll
            for (int half = 0; half < 2; half++) {
                int r = r0 + half * 8;
                float x1 = acc[mt][j][2*half + 0] + bx;
                float x2 = acc[mt][j][2*half + 1] + by;
                if (isK) {
                    float sn, cs;
                    sincosf((float)(r & (SEQ-1)) * inv, &sn, &cs);
                    float o1 = x1*cs - x2*sn;
                    float o2 = x1*sn + x2*cs;
                    float2 of; of.x = o1; of.y = o2;
                    *(float2*)(khout + (size_t)r * HD + col) = of;
                    __nv_bfloat162 hh = __floats2bfloat162_rn(o1, o2);
                    __nv_bfloat162 ll = __floats2bfloat162_rn(
                        o1 - __bfloat162float(hh.x), o2 - __bfloat162float(hh.y));
                    size_t g = (size_t)r * HD + col;
                    *(__nv_bfloat162*)(khi + g) = hh;
                    *(__nv_bfloat162*)(klo + g) = ll;
                } else {
                    float2 of; of.x = x1; of.y = x2;
                    *(float2*)(vhout + (size_t)r * HD + col) = of;
                    int b = r >> 11, s = r & (SEQ-1);
                    __nv_bfloat16 h1 = __float2bfloat16(x1);
                    __nv_bfloat16 h2 = __float2bfloat16(x2);
                    size_t g1 = ((size_t)b*HD + col    ) * SEQ + s;
                    size_t g2 = ((size_t)b*HD + col + 1) * SEQ + s;
                    vthi[g1] = h1;
                    vthi[g2] = h2;
                    vtlo[g1] = __float2bfloat16(x1 - __bfloat162float(h1));
                    vtlo[g2] = __float2bfloat16(x2 - __bfloat162float(h2));
                }
            }
        }
    }
}

// ---------------------------------------------------------------------------
// fp32 -> bf16 hi/lo split (elementwise) — for input x
// ---------------------------------------------------------------------------
__global__ void convert_split(const float* __restrict__ a,
                              __nv_bfloat16* __restrict__ hi,
                              __nv_bfloat16* __restrict__ lo)
{
    size_t i = ((size_t)blockIdx.x * blockDim.x + threadIdx.x) * 4;
    float4 v = *(const float4*)(a + i);
    __nv_bfloat16 h0 = __float2bfloat16(v.x);
    __nv_bfloat16 h1 = __float2bfloat16(v.y);
    __nv_bfloat16 h2 = __float2bfloat16(v.z);
    __nv_bfloat16 h3 = __float2bfloat16(v.w);
    __nv_bfloat162 ph0; ph0.x = h0; ph0.y = h1;
    __nv_bfloat162 ph1; ph1.x = h2; ph1.y = h3;
    __nv_bfloat162 pl0, pl1;
    pl0.x = __float2bfloat16(v.x - __bfloat162float(h0));
    pl0.y = __float2bfloat16(v.y - __bfloat162float(h1));
    pl1.x = __float2bfloat16(v.z - __bfloat162float(h2));
    pl1.y = __float2bfloat16(v.w - __bfloat162float(h3));
    *(__nv_bfloat162*)(hi + i)     = ph0;
    *(__nv_bfloat162*)(hi + i + 2) = ph1;
    *(__nv_bfloat162*)(lo + i)     = pl0;
    *(__nv_bfloat162*)(lo + i + 2) = pl1;
}

// ---------------------------------------------------------------------------
// weight transpose + split:  w[K,N] fp32  ->  hi/lo[N,K] bf16
// ---------------------------------------------------------------------------
__global__ void transpose_split(const float* __restrict__ w,
                                __nv_bfloat16* __restrict__ hi,
                                __nv_bfloat16* __restrict__ lo,
                                int K, int N)
{
    __shared__ float tile[32][33];
    const int k0 = blockIdx.x * 32, n0 = blockIdx.y * 32;
    const int tx = threadIdx.x, ty = threadIdx.y;   // 32 x 8
    #pragma unroll
    for (int i = 0; i < 32; i += 8)
        tile[ty + i][tx] = w[(size_t)(k0 + ty + i) * N + n0 + tx];
    __syncthreads();
    #pragma unroll
    for (int i = 0; i < 32; i += 8) {
        float v = tile[tx][ty + i];
        __nv_bfloat16 h = __float2bfloat16(v);
        size_t o = (size_t)(n0 + ty + i) * K + k0 + tx;
        hi[o] = h;
        lo[o] = __float2bfloat16(v - __bfloat162float(h));
    }
}

// ---------------------------------------------------------------------------
// Tensor-core causal MQA flash attention (bf16x3, fp32 softmax).
// 3-stage KV ring (stage 2 overlays the Q staging region), one sync per tile.
// Output written directly as bf16 hi/lo (feeds gemm_out).
// ---------------------------------------------------------------------------
#define ATT_SCALE 0.08838834764831845f
#define PQ  136                    // Q/K smem pitch (bf16 elems)
#define QELEMS (2*128*PQ)          // 34816 elems
#define KVBUF  (2*64*PQ + 2*128*64) // K hi+lo padded, V hi+lo SW128: 33792 elems

__global__ void __launch_bounds__(256) flash_tc(
    const __nv_bfloat16* __restrict__ Qhi, const __nv_bfloat16* __restrict__ Qlo,
    const __nv_bfloat16* __restrict__ Khi, const __nv_bfloat16* __restrict__ Klo,
    const __nv_bfloat16* __restrict__ Vthi, const __nv_bfloat16* __restrict__ Vtlo,
    __nv_bfloat16* __restrict__ Ohi, __nv_bfloat16* __restrict__ Olo)
{
    extern __shared__ __align__(128) __nv_bfloat16 sm[];
    __nv_bfloat16* QH = sm;                    // 128 x PQ (reused as KV stage 2)
    __nv_bfloat16* QL = QH + 128*PQ;

    const int tid = threadIdx.x;
    const int lane = tid & 31, w = tid >> 5;
    const int b = blockIdx.z, h = blockIdx.y;
    const int qb = (int)gridDim.x - 1 - (int)blockIdx.x;   // heavy CTAs first
    const int row0 = qb * 128;
    const int n_tiles = 2*qb + 2;

    auto kvbase = [&](int st) -> __nv_bfloat16* {
        return (st == 2) ? sm : sm + QELEMS + st * KVBUF;
    };

    auto load_kv = [&](int t, int st) {
        __nv_bfloat16* base = kvbase(st);
        const unsigned vb_hi = s2u(base + 2*64*PQ);
        const unsigned vb_lo = vb_hi + 2*128*64;   // bytes: 128*64*2
        const int kb = t * 64;
        #pragma unroll
        for (int tt = 0; tt < 4; tt++) {
            int u = tid + tt*256;
            {   // K: 64 rows x 128 cols, padded pitch
                int r = u >> 4, c = (u & 15) * 8;
                size_t g = ((size_t)b*SEQ + kb + r)*HD + c;
                cpa16(s2u(base + r*PQ + c), Khi + g);
                cpa16(s2u(base + 64*PQ + r*PQ + c), Klo + g);
            }
            {   // V: 128 rows (hd) x 64 cols (kv), SW128 swizzle
                int r = u >> 3, c8 = u & 7;
                size_t g = ((size_t)b*HD + r)*SEQ + kb + c8*8;
                int so = r*128 + c8*16;
                int sw = so ^ ((so >> 3) & 0x70);
                cpa16(vb_hi + sw, Vthi + g);
                cpa16(vb_lo + sw, Vtlo + g);
            }
        }
    };

    // prologue: start KV stages 0,1 (n_tiles >= 2 always)
    load_kv(0, 0); cp_commit();
    load_kv(1, 1); cp_commit();

    // stage Q (hi/lo)
    #pragma unroll
    for (int t = 0; t < 8; t++) {
        int u = tid + t*256;
        int r = u >> 4, c = (u & 15) * 8;
        size_t g = (((size_t)b*SEQ + row0 + r)*NH + h)*HD + c;
        *(uint4*)&QH[r*PQ + c] = *(const uint4*)&Qhi[g];
        *(uint4*)&QL[r*PQ + c] = *(const uint4*)&Qlo[g];
    }
    __syncthreads();

    // Q fragments in registers (warp rows [w*16, w*16+16))
    unsigned qh[8][4], ql[8][4];
    {
        const int ar = w*16 + (lane & 7) + ((lane >> 3) & 1) * 8;
        const int ac = (lane >> 4) * 8;
        #pragma unroll
        for (int kt = 0; kt < 8; kt++) {
            ldmx4(qh[kt], s2u(&QH[ar*PQ + kt*16 + ac]));
            ldmx4(ql[kt], s2u(&QL[ar*PQ + kt*16 + ac]));
        }
    }
    // NOTE: no sync needed here; the t=0 loop sync below orders frag reads
    // before any cp.async into stage 2 (issued after that sync).

    float m0 = -INFINITY, m1 = -INFINITY, l0 = 0.f, l1 = 0.f;
    float o[16][4];
    #pragma unroll
    for (int n = 0; n < 16; n++)
        #pragma unroll
        for (int e = 0; e < 4; e++) o[n][e] = 0.f;

    const int qr0 = row0 + w*16 + (lane >> 2);
    const int qr1 = qr0 + 8;
    const int kcol = 2*(lane & 3);
    const int krow4 = (lane & 7) + ((lane >> 4) & 1) * 8;
    const int kchalf = ((lane >> 3) & 1) * 8;

    for (int t = 0; t < n_tiles; t++) {
        const int kb = t*64;
        if (t + 2 < n_tiles) cp_wait<1>(); else cp_wait<0>();
        __syncthreads();
        if (t + 2 < n_tiles) { load_kv(t + 2, (t + 2) % 3); cp_commit(); }

        __nv_bfloat16* base = kvbase(t % 3);
        __nv_bfloat16* KH = base;
        __nv_bfloat16* KL = base + 64*PQ;
        const unsigned vb_hi = s2u(base + 2*64*PQ);
        const unsigned vb_lo = vb_hi + 2*128*64;

        // S = Q K^T  (bf16x3)
        float s[8][4];
        #pragma unroll
        for (int j = 0; j < 8; j++)
            #pragma unroll
            for (int e = 0; e < 4; e++) s[j][e] = 0.f;

        #pragma unroll
        for (int kt = 0; kt < 8; kt++) {
            #pragma unroll
            for (int jj = 0; jj < 4; jj++) {
                unsigned th[4], tl[4];
                int off = (jj*16 + krow4)*PQ + kt*16 + kchalf;
                ldmx4(th, s2u(&KH[off]));
                ldmx4(tl, s2u(&KL[off]));
                mma_bf16(s[2*jj],   qh[kt], &th[0]);
                mma_bf16(s[2*jj],   qh[kt], &tl[0]);
                mma_bf16(s[2*jj],   ql[kt], &th[0]);
                mma_bf16(s[2*jj+1], qh[kt], &th[2]);
                mma_bf16(s[2*jj+1], qh[kt], &tl[2]);
                mma_bf16(s[2*jj+1], ql[kt], &th[2]);
            }
        }

        // causal mask + scale + row max
        float tm0 = -INFINITY, tm1 = -INFINITY;
        #pragma unroll
        for (int j = 0; j < 8; j++) {
            int c0 = kb + j*8 + kcol;
            s[j][0] = (c0     <= qr0) ? s[j][0]*ATT_SCALE : -INFINITY;
            s[j][1] = (c0 + 1 <= qr0) ? s[j][1]*ATT_SCALE : -INFINITY;
            s[j][2] = (c0     <= qr1) ? s[j][2]*ATT_SCALE : -INFINITY;
            s[j][3] = (c0 + 1 <= qr1) ? s[j][3]*ATT_SCALE : -INFINITY;
            tm0 = fmaxf(tm0, fmaxf(s[j][0], s[j][1]));
            tm1 = fmaxf(tm1, fmaxf(s[j][2], s[j][3]));
        }
        tm0 = fmaxf(tm0, __shfl_xor_sync(0xffffffffu, tm0, 1));
        tm0 = fmaxf(tm0, __shfl_xor_sync(0xffffffffu, tm0, 2));
        tm1 = fmaxf(tm1, __shfl_xor_sync(0xffffffffu, tm1, 1));
        tm1 = fmaxf(tm1, __shfl_xor_sync(0xffffffffu, tm1, 2));

        float mn0 = fmaxf(m0, tm0), mn1 = fmaxf(m1, tm1);
        float rs0 = 0.f, rs1 = 0.f;
        unsigned pH[8][2], pL[8][2];
        #pragma unroll
        for (int j = 0; j < 8; j++) {
            float p0 = __expf(s[j][0] - mn0), p1 = __expf(s[j][1] - mn0);
            float p2 = __expf(s[j][2] - mn1), p3 = __expf(s[j][3] - mn1);
            rs0 += p0 + p1; rs1 += p2 + p3;
            __nv_bfloat162 h01 = __floats2bfloat162_rn(p0, p1);
            __nv_bfloat162 h23 = __floats2bfloat162_rn(p2, p3);
            pH[j][0] = *(unsigned*)&h01;
            pH[j][1] = *(unsigned*)&h23;
            pL[j][0] = pack_bf16(p0 - __bfloat162float(h01.x),
                                 p1 - __bfloat162float(h01.y));
            pL[j][1] = pack_bf16(p2 - __bfloat162float(h23.x),
                                 p3 - __bfloat162float(h23.y));
        }
        rs0 += __shfl_xor_sync(0xffffffffu, rs0, 1);
        rs0 += __shfl_xor_sync(0xffffffffu, rs0, 2);
        rs1 += __shfl_xor_sync(0xffffffffu, rs1, 1);
        rs1 += __shfl_xor_sync(0xffffffffu, rs1, 2);

        float al0 = __expf(m0 - mn0), al1 = __expf(m1 - mn1);
        m0 = mn0; m1 = mn1;
        l0 = l0*al0 + rs0; l1 = l1*al1 + rs1;
        #pragma unroll
        for (int n = 0; n < 16; n++) {
            o[n][0] *= al0; o[n][1] *= al0;
            o[n][2] *= al1; o[n][3] *= al1;
        }

        // O += P V  (bf16x3; SW128 V fragments)
        #pragma unroll
        for (int ks = 0; ks < 4; ks++) {
            unsigned aH[4] = {pH[2*ks][0], pH[2*ks][1], pH[2*ks+1][0], pH[2*ks+1][1]};
            unsigned aL[4] = {pL[2*ks][0], pL[2*ks][1], pL[2*ks+1][0], pL[2*ks+1][1]};
            #pragma unroll
            for (int nn = 0; nn < 8; nn++) {
                unsigned vh4[4], vl4[4];
                int so = (nn*16 + krow4)*128 + ks*32 + kchalf*2;
                int sw = so ^ ((so >> 3) & 0x70);
                ldmx4(vh4, vb_hi + sw);
                ldmx4(vl4, vb_lo + sw);
                mma_bf16(o[2*nn],   aH, &vh4[0]);
                mma_bf16(o[2*nn],   aH, &vl4[0]);
                mma_bf16(o[2*nn],   aL, &vh4[0]);
                mma_bf16(o[2*nn+1], aH, &vh4[2]);
                mma_bf16(o[2*nn+1], aH, &vl4[2]);
                mma_bf16(o[2*nn+1], aL, &vh4[2]);
            }
        }
    }

    // epilogue: write bf16 hi/lo directly
    const float i0 = 1.f / l0, i1 = 1.f / l1;
    #pragma unroll
    for (int n = 0; n < 16; n++) {
        int col = n*8 + kcol;
        size_t g0 = (((size_t)b*SEQ + qr0)*NH + h)*HD + col;
        size_t g1 = (((size_t)b*SEQ + qr1)*NH + h)*HD + col;
        float a0 = o[n][0]*i0, a1 = o[n][1]*i0;
        float a2 = o[n][2]*i1, a3 = o[n][3]*i1;
        __nv_bfloat162 h0 = __floats2bfloat162_rn(a0, a1);
        __nv_bfloat162 h1 = __floats2bfloat162_rn(a2, a3);
        __nv_bfloat162 l0v = __floats2bfloat162_rn(a0 - __bfloat162float(h0.x),
                                                   a1 - __bfloat162float(h0.y));
        __nv_bfloat162 l1v = __floats2bfloat162_rn(a2 - __bfloat162float(h1.x),
                                                   a3 - __bfloat162float(h1.y));
        *(__nv_bfloat162*)(Ohi + g0) = h0;
        *(__nv_bfloat162*)(Olo + g0) = l0v;
        *(__nv_bfloat162*)(Ohi + g1) = h1;
        *(__nv_bfloat162*)(Olo + g1) = l1v;
    }
}

// ---------------------------------------------------------------------------
extern "C" void kernel_launch(void* const* d_in, const int* in_sizes, int n_in,
                              void* d_out, int out_size)
{
    const float* x  = (const float*)d_in[0];
    const float* wq = (const float*)d_in[1];
    const float* bq = (const float*)d_in[2];
    const float* wk = (const float*)d_in[3];
    const float* bk = (const float*)d_in[4];
    const float* wv = (const float*)d_in[5];
    const float* bv = (const float*)d_in[6];
    const float* wo = (const float*)d_in[7];
    const float* bo = (const float*)d_in[8];

    float* out = (float*)d_out;                      // (B,S,D)
    float* kh  = out + (size_t)MROWS*DM;             // (B,1,S,HD)
    float* vh  = kh  + (size_t)MROWS*HD;             // (B,1,S,HD)

    __nv_bfloat16 *ahi, *alo, *wqh, *wql, *wkh, *wkl, *wvh, *wvl, *woh, *wol;
    __nv_bfloat16 *qhi, *qlo, *khi, *klo, *vthi, *vtlo;
    cudaGetSymbolAddress((void**)&ahi, g_ahi);
    cudaGetSymbolAddress((void**)&alo, g_alo);
    cudaGetSymbolAddress((void**)&wqh, g_wqT_hi);
    cudaGetSymbolAddress((void**)&wql, g_wqT_lo);
    cudaGetSymbolAddress((void**)&wkh, g_wkT_hi);
    cudaGetSymbolAddress((void**)&wkl, g_wkT_lo);
    cudaGetSymbolAddress((void**)&wvh, g_wvT_hi);
    cudaGetSymbolAddress((void**)&wvl, g_wvT_lo);
    cudaGetSymbolAddress((void**)&woh, g_woT_hi);
    cudaGetSymbolAddress((void**)&wol, g_woT_lo);
    cudaGetSymbolAddress((void**)&qhi, g_qhi);
    cudaGetSymbolAddress((void**)&qlo, g_qlo);
    cudaGetSymbolAddress((void**)&khi, g_khi);
    cudaGetSymbolAddress((void**)&klo, g_klo);
    cudaGetSymbolAddress((void**)&vthi, g_vthi);
    cudaGetSymbolAddress((void**)&vtlo, g_vtlo);

    const int GEMM_SMEM  = 3 * 65536;                 // 196,608 B
    const int FLASH_SMEM = (QELEMS + 2*KVBUF) * 2;    // 204,800 B
    cudaFuncSetAttribute(gemm_out, cudaFuncAttributeMaxDynamicSharedMemorySize, GEMM_SMEM);
    cudaFuncSetAttribute(gemm_q,   cudaFuncAttributeMaxDynamicSharedMemorySize, GEMM_SMEM);
    cudaFuncSetAttribute(gemm_kv,  cudaFuncAttributeMaxDynamicSharedMemorySize, GEMM_SMEM);
    cudaFuncSetAttribute(flash_tc, cudaFuncAttributeMaxDynamicSharedMemorySize, FLASH_SMEM);

    // split input + weights to bf16 hi/lo
    convert_split<<<(size_t)MROWS*DM/1024, 256>>>(x, ahi, alo);
    transpose_split<<<dim3(DM/32, DM/32), dim3(32,8)>>>(wq, wqh, wql, DM, DM);
    transpose_split<<<dim3(DM/32, HD/32), dim3(32,8)>>>(wk, wkh, wkl, DM, HD);
    transpose_split<<<dim3(DM/32, HD/32), dim3(32,8)>>>(wv, wvh, wvl, DM, HD);
    transpose_split<<<dim3(DM/32, DM/32), dim3(32,8)>>>(wo, woh, wol, DM, DM);

    // projections (rope/split/transpose fused in epilogues)
    gemm_q <<<dim3(DM/128, MROWS/128), 256, GEMM_SMEM>>>(ahi, alo, wqh, wql, bq, qhi, qlo);
    gemm_kv<<<dim3(2,      MROWS/128), 256, GEMM_SMEM>>>(ahi, alo, wkh, wkl, wvh, wvl,
                                                         bk, bv, kh, khi, klo, vh, vthi, vtlo);

    // attention (writes bf16 hi/lo directly)
    flash_tc<<<dim3(16, 16, 4), 256, FLASH_SMEM>>>(qhi, qlo, khi, klo, vthi, vtlo, ahi, alo);

    // output projection
    gemm_out<<<dim3(DM/128, MROWS/128), 256, GEMM_SMEM>>>(ahi, alo, woh, wol, bo, out);
}